// round 7
// baseline (speedup 1.0000x reference)
#include <cuda_runtime.h>
#include <cuda_bf16.h>
#include <math.h>

// Problem constants
constexpr int B_   = 2;
constexpr int S_   = 2048;
constexpr int DIM_ = 4096;
constexpr int NH_  = 32;
constexpr int NKV_ = 8;
constexpr int HD_  = 128;

// ---------------------------------------------------------------------------
// Scratch (module-scope device arrays; allocation-free at launch time)
// ---------------------------------------------------------------------------
__device__ __nv_bfloat16 g_xhi[16777216],  g_xlo[16777216];     // x split
__device__ __nv_bfloat16 g_wqhi[16777216], g_wqlo[16777216];
__device__ __nv_bfloat16 g_wkhi[4194304],  g_wklo[4194304];
__device__ __nv_bfloat16 g_wvhi[4194304],  g_wvlo[4194304];
__device__ __nv_bfloat16 g_wohi[16777216], g_wolo[16777216];
__device__ float         g_qf[16777216];                        // q fp32 (pre-rope)
__device__ float         g_kf[4194304];
__device__ float         g_vf[4194304];
__device__ __nv_bfloat16 g_qhi[16777216], g_qlo[16777216];      // post-rope split
__device__ __nv_bfloat16 g_khi[4194304],  g_klo[4194304];
__device__ __nv_bfloat16 g_vthi[4194304], g_vtlo[4194304];      // V transposed [b,kv,d,s]
__device__ float         g_sc[268435456];                       // scores fp32 [b,h,q,k]
__device__ __nv_bfloat16 g_phi[268435456], g_plo[268435456];    // probs split
__device__ __nv_bfloat16 g_ahi[16777216],  g_alo[16777216];     // attn split [b,s,h,d]

// ---------------------------------------------------------------------------
// PTX helpers — sm_80-era only (compute_103 virtual arch: NO tcgen05)
// ---------------------------------------------------------------------------
__device__ __forceinline__ unsigned smem_u32(const void* p) {
    return (unsigned)__cvta_generic_to_shared(p);
}
__device__ __forceinline__ void cpa16(unsigned dst, const void* src) {
    asm volatile("cp.async.cg.shared.global [%0], [%1], 16;" :: "r"(dst), "l"(src) : "memory");
}
__device__ __forceinline__ void cpa_commit() {
    asm volatile("cp.async.commit_group;" ::: "memory");
}
__device__ __forceinline__ void cpa_wait1() {
    asm volatile("cp.async.wait_group 1;" ::: "memory");
}
__device__ __forceinline__ void cpa_wait0() {
    asm volatile("cp.async.wait_group 0;" ::: "memory");
}
__device__ __forceinline__ void ldsm4(unsigned* r, unsigned a) {
    asm volatile("ldmatrix.sync.aligned.m8n8.x4.shared.b16 {%0,%1,%2,%3}, [%4];"
                 : "=r"(r[0]), "=r"(r[1]), "=r"(r[2]), "=r"(r[3]) : "r"(a));
}
__device__ __forceinline__ void mma16816(float* c, const unsigned* a, const unsigned* b) {
    asm volatile("mma.sync.aligned.m16n8k16.row.col.f32.bf16.bf16.f32 "
                 "{%0,%1,%2,%3}, {%4,%5,%6,%7}, {%8,%9}, {%0,%1,%2,%3};"
                 : "+f"(c[0]), "+f"(c[1]), "+f"(c[2]), "+f"(c[3])
                 : "r"(a[0]), "r"(a[1]), "r"(a[2]), "r"(a[3]), "r"(b[0]), "r"(b[1]));
}

// SMEM geometry: 64B rows (32 bf16), XOR swizzle on the 16B segment:
//   seg' = (seg + (row>>1)) & 3
// Conflict-free for cp.async 16B writes (each warp covers 8 rows x 4 segs once)
// and for every ldmatrix 8-lane phase (8 consecutive rows, fixed seg ->
// (row&1, seg') covers 8 distinct 16B slots in 128B).
constexpr int SUBT    = 128 * 64;      // 8192 B per operand subtile
constexpr int STAGE   = 4 * SUBT;      // Ahi|Alo|Bhi|Blo = 32768 B
constexpr int SMEM_SZ = 3 * STAGE;     // triple buffered = 98304 B

__device__ __forceinline__ unsigned swz64(int row, int seg) {
    return (unsigned)(row * 64 + (((seg + (row >> 1)) & 3) << 4));
}

// ---------------------------------------------------------------------------
// bf16 split GEMM via mma.sync: C[m,n] = scale * sum_k A[m,k]*B[n,k]
//   A = Ahi+Alo, B = Bhi+Blo (hi/lo split of fp32), both K-major [rows, K].
//   3 passes accumulated in fp32 regs: hi*hi + hi*lo + lo*hi  (pass-major
//   emission: dependency distance 4 between mmas on the same accumulator).
//   EPI=0: fp32 C.  EPI=1: hi/lo bf16 split C.
//   causal=1: skip tiles above diagonal.  kcap=1: K capped at bm0+128.
//   3-stage pipeline, single barrier per chunk, 2 CTAs/SM.
// ---------------------------------------------------------------------------
template <int EPI>
__global__ __launch_bounds__(256, 2)
void gemm_mma(const __nv_bfloat16* __restrict__ Ahi, const __nv_bfloat16* __restrict__ Alo,
              const __nv_bfloat16* __restrict__ Bhi, const __nv_bfloat16* __restrict__ Blo,
              float* __restrict__ Cf,
              __nv_bfloat16* __restrict__ Chi, __nv_bfloat16* __restrict__ Clo,
              int K, int lda, int ldb, int ldc,
              int zdiv, int bdiv,
              long long sA1, long long sA2, long long sB1, long long sB2,
              long long sC1, long long sC2,
              float scale, int causal, int kcap)
{
    const int bm0 = blockIdx.y * 128;
    const int bn0 = blockIdx.x * 128;
    if (causal && bn0 > bm0) return;

    const int z  = blockIdx.z;
    const int z2 = z / zdiv;
    const int z1 = z - z2 * zdiv;
    const __nv_bfloat16* Ah = Ahi + z2 * sA2 + (long long)z1 * sA1;
    const __nv_bfloat16* Al = Alo + z2 * sA2 + (long long)z1 * sA1;
    const __nv_bfloat16* Bh = Bhi + z2 * sB2 + (long long)(z1 / bdiv) * sB1;
    const __nv_bfloat16* Bl = Blo + z2 * sB2 + (long long)(z1 / bdiv) * sB1;
    const long long coff = z2 * sC2 + (long long)z1 * sC1;

    extern __shared__ char smem[];
    const unsigned sb = smem_u32(smem);
    const int tid  = threadIdx.x;
    const int lane = tid & 31;
    const int wid  = tid >> 5;
    const int wm   = wid & 3;     // 4 warp-rows x 32
    const int wn   = wid >> 2;    // 2 warp-cols x 64

    int Keff = K;
    if (kcap) { int c = bm0 + 128; if (c < Keff) Keff = c; }
    const int nk = Keff >> 5;     // KC = 32

    auto stage = [&](int si) {
        const unsigned base = sb + (si % 3) * STAGE;
        const int kc = si * 32;
        #pragma unroll
        for (int it = 0; it < 8; it++) {
            const int sub = it >> 1;                 // 0:Ahi 1:Alo 2:Bhi 3:Blo
            const int w   = (tid + it * 256) & 511;
            const int row = w >> 2, seg = w & 3;     // 4 x 16B per 64B row
            const __nv_bfloat16* src;
            if      (sub == 0) src = Ah + (long long)(bm0 + row) * lda + kc + seg * 8;
            else if (sub == 1) src = Al + (long long)(bm0 + row) * lda + kc + seg * 8;
            else if (sub == 2) src = Bh + (long long)(bn0 + row) * ldb + kc + seg * 8;
            else               src = Bl + (long long)(bn0 + row) * ldb + kc + seg * 8;
            cpa16(base + sub * SUBT + swz64(row, seg), src);
        }
    };

    float acc[2][8][4];
    #pragma unroll
    for (int i = 0; i < 2; i++)
        #pragma unroll
        for (int j = 0; j < 8; j++)
            #pragma unroll
            for (int e = 0; e < 4; e++) acc[i][j][e] = 0.0f;

    stage(0); cpa_commit();
    stage(1); cpa_commit();

    // ldmatrix lane address components (constant across chunks)
    const int arow = wm * 32 + (lane & 15);          // + mt*16
    const int asel = (lane >> 4);                    // 16B chunk within kstep
    const int brow = wn * 64 + (lane & 7) + ((lane >> 4) << 3);  // + pr*16
    const int bsel = (lane >> 3) & 1;

    for (int i = 0; i < nk; i++) {
        if (i + 1 < nk) cpa_wait1(); else cpa_wait0();
        __syncthreads();
        const unsigned base = sb + (i % 3) * STAGE;

        #pragma unroll
        for (int ks = 0; ks < 2; ks++) {
            unsigned ah[2][4], al[2][4];
            #pragma unroll
            for (int mt = 0; mt < 2; mt++) {
                const int r = arow + mt * 16;
                const unsigned off = swz64(r, ks * 2 + asel);
                ldsm4(ah[mt], base + off);
                ldsm4(al[mt], base + SUBT + off);
            }
            #pragma unroll
            for (int pr = 0; pr < 4; pr++) {
                unsigned bh[4], bl[4];
                const int r = brow + pr * 16;
                const unsigned off = swz64(r, ks * 2 + bsel);
                ldsm4(bh, base + 2 * SUBT + off);
                ldsm4(bl, base + 3 * SUBT + off);
                // pass-major: all 4 accs hh, then hl, then lh  (dep distance 4)
                #pragma unroll
                for (int mt = 0; mt < 2; mt++)
                    #pragma unroll
                    for (int hf = 0; hf < 2; hf++)
                        mma16816(acc[mt][pr * 2 + hf], ah[mt], &bh[hf * 2]);
                #pragma unroll
                for (int mt = 0; mt < 2; mt++)
                    #pragma unroll
                    for (int hf = 0; hf < 2; hf++)
                        mma16816(acc[mt][pr * 2 + hf], ah[mt], &bl[hf * 2]);
                #pragma unroll
                for (int mt = 0; mt < 2; mt++)
                    #pragma unroll
                    for (int hf = 0; hf < 2; hf++)
                        mma16816(acc[mt][pr * 2 + hf], al[mt], &bh[hf * 2]);
            }
        }
        // 3-stage ring: buffer (i+2)%3 was consumed at iter i-1; the barrier at
        // the top of THIS iter already ordered all warps past it -> no 2nd sync.
        if (i + 2 < nk) { stage(i + 2); cpa_commit(); }
    }

    // Epilogue: register accumulators -> global (float2 / bf16x2 stores)
    const int er = bm0 + wm * 32 + (lane >> 2);
    const int ec = bn0 + wn * 64 + (lane & 3) * 2;
    #pragma unroll
    for (int mt = 0; mt < 2; mt++)
        #pragma unroll
        for (int nt = 0; nt < 8; nt++) {
            const float* c = acc[mt][nt];
            const int row = er + mt * 16;
            const int col = ec + nt * 8;
            const long long gi0 = coff + (long long)row * ldc + col;
            const long long gi1 = coff + (long long)(row + 8) * ldc + col;
            if (EPI == 0) {
                *(float2*)(Cf + gi0) = make_float2(c[0] * scale, c[1] * scale);
                *(float2*)(Cf + gi1) = make_float2(c[2] * scale, c[3] * scale);
            } else {
                float v0 = c[0] * scale, v1 = c[1] * scale;
                float v2 = c[2] * scale, v3 = c[3] * scale;
                __nv_bfloat16 h0 = __float2bfloat16(v0), h1 = __float2bfloat16(v1);
                __nv_bfloat16 h2 = __float2bfloat16(v2), h3 = __float2bfloat16(v3);
                *(__nv_bfloat162*)(Chi + gi0) = __halves2bfloat162(h0, h1);
                *(__nv_bfloat162*)(Chi + gi1) = __halves2bfloat162(h2, h3);
                *(__nv_bfloat162*)(Clo + gi0) = __halves2bfloat162(
                    __float2bfloat16(v0 - __bfloat162float(h0)),
                    __float2bfloat16(v1 - __bfloat162float(h1)));
                *(__nv_bfloat162*)(Clo + gi1) = __halves2bfloat162(
                    __float2bfloat16(v2 - __bfloat162float(h2)),
                    __float2bfloat16(v3 - __bfloat162float(h3)));
            }
        }
}

// ---------------------------------------------------------------------------
// Elementwise fp32 -> (hi, lo) bf16 split
// ---------------------------------------------------------------------------
__global__ __launch_bounds__(256)
void split_k(const float4* __restrict__ s, __nv_bfloat162* __restrict__ h2,
             __nv_bfloat162* __restrict__ l2, int n4)
{
    int i = blockIdx.x * 256 + threadIdx.x;
    if (i >= n4) return;
    float4 v = s[i];
    __nv_bfloat16 hx = __float2bfloat16(v.x), hy = __float2bfloat16(v.y);
    __nv_bfloat16 hz = __float2bfloat16(v.z), hw = __float2bfloat16(v.w);
    h2[2 * i]     = __halves2bfloat162(hx, hy);
    h2[2 * i + 1] = __halves2bfloat162(hz, hw);
    l2[2 * i]     = __halves2bfloat162(__float2bfloat16(v.x - __bfloat162float(hx)),
                                       __float2bfloat16(v.y - __bfloat162float(hy)));
    l2[2 * i + 1] = __halves2bfloat162(__float2bfloat16(v.z - __bfloat162float(hz)),
                                       __float2bfloat16(v.w - __bfloat162float(hw)));
}

// ---------------------------------------------------------------------------
// RoPE + split: reads fp32 [B,S,nh,HD], writes hi/lo bf16 same layout
// ---------------------------------------------------------------------------
__global__ __launch_bounds__(256)
void rope_split_k(const float* __restrict__ t, int nh,
                  const float* __restrict__ cs, const float* __restrict__ sn,
                  __nv_bfloat16* __restrict__ hi, __nv_bfloat16* __restrict__ lo)
{
    long long idx = (long long)blockIdx.x * 256 + threadIdx.x;
    const long long total = (long long)B_ * S_ * nh * (HD_ / 2);
    if (idx >= total) return;
    const int i = (int)(idx & 63);
    long long r = idx >> 6;
    const int h = (int)(r % nh); r /= nh;
    const int s = (int)(r % S_);
    const long long b = r / S_;

    const float c  = cs[s * 64 + i];
    const float si = sn[s * 64 + i];
    const long long off = (((b * S_ + s) * nh + h) * (long long)HD_) + 2 * i;
    const float t0 = t[off], t1 = t[off + 1];
    const float o0 = t0 * c - t1 * si;
    const float o1 = t0 * si + t1 * c;
    __nv_bfloat16 h0 = __float2bfloat16(o0);
    __nv_bfloat16 h1 = __float2bfloat16(o1);
    hi[off] = h0;     lo[off]     = __float2bfloat16(o0 - __bfloat162float(h0));
    hi[off + 1] = h1; lo[off + 1] = __float2bfloat16(o1 - __bfloat162float(h1));
}

// ---------------------------------------------------------------------------
// V transpose + split: vf32 [b,s,kv,d] -> vt hi/lo [b,kv,d,s]
// ---------------------------------------------------------------------------
__global__ __launch_bounds__(256)
void tsplit_v_k(const float* __restrict__ v,
                __nv_bfloat16* __restrict__ hi, __nv_bfloat16* __restrict__ lo)
{
    __shared__ float tile[32][33];
    const int bz = blockIdx.z;
    const int b = bz >> 3, kv = bz & 7;
    const int s0 = blockIdx.x * 32, d0 = blockIdx.y * 32;
    const int tx = threadIdx.x & 31, ty = threadIdx.x >> 5;

    #pragma unroll
    for (int j = 0; j < 4; j++) {
        int s = s0 + ty + j * 8;
        tile[ty + j * 8][tx] = v[((size_t)(b * S_ + s) * NKV_ + kv) * HD_ + d0 + tx];
    }
    __syncthreads();
    #pragma unroll
    for (int j = 0; j < 4; j++) {
        int d = d0 + ty + j * 8;
        float val = tile[tx][ty + j * 8];
        size_t o = ((size_t)(b * NKV_ + kv) * HD_ + d) * S_ + s0 + tx;
        __nv_bfloat16 h = __float2bfloat16(val);
        hi[o] = h;
        lo[o] = __float2bfloat16(val - __bfloat162float(h));
    }
}

// ---------------------------------------------------------------------------
// Causal softmax: fp32 scores row -> hi/lo bf16 probs. Zero-fills only up to
// the next 128-col boundary — the PV GEMM's kcap never reads beyond it.
// ---------------------------------------------------------------------------
__global__ __launch_bounds__(256)
void softmax_k(const float* __restrict__ sc,
               __nv_bfloat16* __restrict__ phi, __nv_bfloat16* __restrict__ plo)
{
    const long long row = blockIdx.x;
    const int q = (int)(row % S_);
    const float* p = sc + row * (long long)S_;
    __nv_bfloat16* oh = phi + row * (long long)S_;
    __nv_bfloat16* ol = plo + row * (long long)S_;
    const int L = q + 1;
    const int tid = threadIdx.x;
    __shared__ float red[8];

    float m = -1e30f;
    for (int i = tid; i < L; i += 256) m = fmaxf(m, p[i]);
    #pragma unroll
    for (int o = 16; o; o >>= 1) m = fmaxf(m, __shfl_xor_sync(0xffffffffu, m, o));
    if ((tid & 31) == 0) red[tid >> 5] = m;
    __syncthreads();
    m = red[0];
    #pragma unroll
    for (int i = 1; i < 8; i++) m = fmaxf(m, red[i]);
    __syncthreads();

    float s = 0.0f;
    for (int i = tid; i < L; i += 256) s += expf(p[i] - m);
    #pragma unroll
    for (int o = 16; o; o >>= 1) s += __shfl_xor_sync(0xffffffffu, s, o);
    if ((tid & 31) == 0) red[tid >> 5] = s;
    __syncthreads();
    s = red[0];
    #pragma unroll
    for (int i = 1; i < 8; i++) s += red[i];

    const float inv = 1.0f / s;
    for (int i = tid; i < L; i += 256) {
        float e = expf(p[i] - m) * inv;
        __nv_bfloat16 h = __float2bfloat16(e);
        oh[i] = h;
        ol[i] = __float2bfloat16(e - __bfloat162float(h));
    }
    const int zend = ((q >> 7) + 1) << 7;   // next 128 boundary (= PV kcap limit)
    const __nv_bfloat16 z = __float2bfloat16(0.0f);
    for (int i = L + tid; i < zend; i += 256) { oh[i] = z; ol[i] = z; }
}

// ---------------------------------------------------------------------------
// Inputs (metadata order): x, wq, wk, wv, wo, freqs_cos, freqs_sin
// ---------------------------------------------------------------------------
extern "C" void kernel_launch(void* const* d_in, const int* in_sizes, int n_in,
                              void* d_out, int out_size)
{
    const float* x  = (const float*)d_in[0];
    const float* wq = (const float*)d_in[1];
    const float* wk = (const float*)d_in[2];
    const float* wv = (const float*)d_in[3];
    const float* wo = (const float*)d_in[4];
    const float* fc = (const float*)d_in[5];
    const float* fs = (const float*)d_in[6];
    float* out = (float*)d_out;

    __nv_bfloat16 *xhi, *xlo, *wqhi, *wqlo, *wkhi, *wklo, *wvhi, *wvlo, *wohi, *wolo;
    __nv_bfloat16 *qhi, *qlo, *khi, *klo, *vthi, *vtlo, *phi, *plo, *ahi, *alo;
    float *qf, *kf, *vf, *sp;
    cudaGetSymbolAddress((void**)&xhi,  g_xhi);  cudaGetSymbolAddress((void**)&xlo,  g_xlo);
    cudaGetSymbolAddress((void**)&wqhi, g_wqhi); cudaGetSymbolAddress((void**)&wqlo, g_wqlo);
    cudaGetSymbolAddress((void**)&wkhi, g_wkhi); cudaGetSymbolAddress((void**)&wklo, g_wklo);
    cudaGetSymbolAddress((void**)&wvhi, g_wvhi); cudaGetSymbolAddress((void**)&wvlo, g_wvlo);
    cudaGetSymbolAddress((void**)&wohi, g_wohi); cudaGetSymbolAddress((void**)&wolo, g_wolo);
    cudaGetSymbolAddress((void**)&qf, g_qf);
    cudaGetSymbolAddress((void**)&kf, g_kf);
    cudaGetSymbolAddress((void**)&vf, g_vf);
    cudaGetSymbolAddress((void**)&qhi, g_qhi);   cudaGetSymbolAddress((void**)&qlo, g_qlo);
    cudaGetSymbolAddress((void**)&khi, g_khi);   cudaGetSymbolAddress((void**)&klo, g_klo);
    cudaGetSymbolAddress((void**)&vthi, g_vthi); cudaGetSymbolAddress((void**)&vtlo, g_vtlo);
    cudaGetSymbolAddress((void**)&sp, g_sc);
    cudaGetSymbolAddress((void**)&phi, g_phi);   cudaGetSymbolAddress((void**)&plo, g_plo);
    cudaGetSymbolAddress((void**)&ahi, g_ahi);   cudaGetSymbolAddress((void**)&alo, g_alo);

    cudaFuncSetAttribute(gemm_mma<0>, cudaFuncAttributeMaxDynamicSharedMemorySize, SMEM_SZ);
    cudaFuncSetAttribute(gemm_mma<1>, cudaFuncAttributeMaxDynamicSharedMemorySize, SMEM_SZ);

    const float scale = 0.08838834764831845f;  // 1/sqrt(128)

    // 1) split inputs into bf16 hi/lo
    split_k<<<16384, 256>>>((const float4*)x,  (__nv_bfloat162*)xhi,  (__nv_bfloat162*)xlo,  4194304);
    split_k<<<16384, 256>>>((const float4*)wq, (__nv_bfloat162*)wqhi, (__nv_bfloat162*)wqlo, 4194304);
    split_k<<<4096,  256>>>((const float4*)wk, (__nv_bfloat162*)wkhi, (__nv_bfloat162*)wklo, 1048576);
    split_k<<<4096,  256>>>((const float4*)wv, (__nv_bfloat162*)wvhi, (__nv_bfloat162*)wvlo, 1048576);
    split_k<<<16384, 256>>>((const float4*)wo, (__nv_bfloat162*)wohi, (__nv_bfloat162*)wolo, 4194304);

    // 2) projections (fp32 out)
    gemm_mma<0><<<dim3(32, 32, 1), 256, SMEM_SZ>>>(
        xhi, xlo, wqhi, wqlo, qf, nullptr, nullptr,
        DIM_, DIM_, DIM_, DIM_, 1, 1, 0, 0, 0, 0, 0, 0, 1.0f, 0, 0);
    gemm_mma<0><<<dim3(8, 32, 1), 256, SMEM_SZ>>>(
        xhi, xlo, wkhi, wklo, kf, nullptr, nullptr,
        DIM_, DIM_, DIM_, NKV_ * HD_, 1, 1, 0, 0, 0, 0, 0, 0, 1.0f, 0, 0);
    gemm_mma<0><<<dim3(8, 32, 1), 256, SMEM_SZ>>>(
        xhi, xlo, wvhi, wvlo, vf, nullptr, nullptr,
        DIM_, DIM_, DIM_, NKV_ * HD_, 1, 1, 0, 0, 0, 0, 0, 0, 1.0f, 0, 0);

    // 3) RoPE + split (q, k); V transpose + split
    rope_split_k<<<32768, 256>>>(qf, NH_, fc, fs, qhi, qlo);
    rope_split_k<<<8192, 256>>>(kf, NKV_, fc, fs, khi, klo);
    tsplit_v_k<<<dim3(S_ / 32, HD_ / 32, B_ * NKV_), 256>>>(vf, vthi, vtlo);

    // 4) scores = scale * Q K^T  (causal tile skip)
    gemm_mma<0><<<dim3(16, 16, B_ * NH_), 256, SMEM_SZ>>>(
        qhi, qlo, khi, klo, sp, nullptr, nullptr,
        HD_, NH_ * HD_, NKV_ * HD_, S_,
        NH_, 4,
        (long long)HD_, (long long)S_ * NH_ * HD_,
        (long long)HD_, (long long)S_ * NKV_ * HD_,
        (long long)S_ * S_, (long long)NH_ * S_ * S_,
        scale, 1, 0);

    // 5) softmax -> split probs
    softmax_k<<<B_ * NH_ * S_, 256>>>(sp, phi, plo);

    // 6) attn = P V  (K capped causally; split epilogue)
    gemm_mma<1><<<dim3(1, 16, B_ * NH_), 256, SMEM_SZ>>>(
        phi, plo, vthi, vtlo, nullptr, ahi, alo,
        S_, S_, S_, NH_ * HD_,
        NH_, 4,
        (long long)S_ * S_, (long long)NH_ * S_ * S_,
        (long long)HD_ * S_, (long long)NKV_ * HD_ * S_,
        (long long)HD_, (long long)S_ * NH_ * HD_,
        1.0f, 0, 1);

    // 7) output projection
    gemm_mma<0><<<dim3(32, 32, 1), 256, SMEM_SZ>>>(
        ahi, alo, wohi, wolo, out, nullptr, nullptr,
        DIM_, DIM_, DIM_, DIM_, 1, 1, 0, 0, 0, 0, 0, 0, 1.0f, 0, 0);
}

// round 8
// speedup vs baseline: 1.7070x; 1.7070x over previous
#include <cuda_runtime.h>
#include <cuda_fp16.h>
#include <math.h>

// Problem constants
constexpr int B_   = 2;
constexpr int S_   = 2048;
constexpr int DIM_ = 4096;
constexpr int NH_  = 32;
constexpr int NKV_ = 8;
constexpr int HD_  = 128;

// ---------------------------------------------------------------------------
// Scratch (module-scope device arrays; allocation-free at launch time)
// ---------------------------------------------------------------------------
__device__ __half g_xhi[16777216],  g_xlo[16777216];     // x split
__device__ __half g_wqhi[16777216], g_wqlo[16777216];
__device__ __half g_wkhi[4194304],  g_wklo[4194304];
__device__ __half g_wvhi[4194304],  g_wvlo[4194304];
__device__ __half g_wohi[16777216], g_wolo[16777216];
__device__ float  g_qf[16777216];                        // q fp32 (pre-rope)
__device__ float  g_kf[4194304];
__device__ float  g_vf[4194304];
__device__ __half g_qhi[16777216], g_qlo[16777216];      // post-rope split
__device__ __half g_khi[4194304],  g_klo[4194304];
__device__ __half g_vthi[4194304], g_vtlo[4194304];      // V transposed [b,kv,d,s]
__device__ float  g_sc[268435456];                       // scores fp32 [b,h,q,k]
__device__ __half g_phi[268435456], g_plo[268435456];    // probs split
__device__ __half g_ahi[16777216],  g_alo[16777216];     // attn split [b,s,h,d]

// ---------------------------------------------------------------------------
// PTX helpers — sm_80-era only (compute_103 virtual arch: NO tcgen05)
// ---------------------------------------------------------------------------
__device__ __forceinline__ unsigned smem_u32(const void* p) {
    return (unsigned)__cvta_generic_to_shared(p);
}
__device__ __forceinline__ void cpa16(unsigned dst, const void* src) {
    asm volatile("cp.async.cg.shared.global [%0], [%1], 16;" :: "r"(dst), "l"(src) : "memory");
}
__device__ __forceinline__ void cpa_commit() {
    asm volatile("cp.async.commit_group;" ::: "memory");
}
__device__ __forceinline__ void cpa_wait1() {
    asm volatile("cp.async.wait_group 1;" ::: "memory");
}
__device__ __forceinline__ void cpa_wait0() {
    asm volatile("cp.async.wait_group 0;" ::: "memory");
}
__device__ __forceinline__ void ldsm4(unsigned* r, unsigned a) {
    asm volatile("ldmatrix.sync.aligned.m8n8.x4.shared.b16 {%0,%1,%2,%3}, [%4];"
                 : "=r"(r[0]), "=r"(r[1]), "=r"(r[2]), "=r"(r[3]) : "r"(a));
}
__device__ __forceinline__ void mma16816(float* c, const unsigned* a, const unsigned* b) {
    asm volatile("mma.sync.aligned.m16n8k16.row.col.f32.f16.f16.f32 "
                 "{%0,%1,%2,%3}, {%4,%5,%6,%7}, {%8,%9}, {%0,%1,%2,%3};"
                 : "+f"(c[0]), "+f"(c[1]), "+f"(c[2]), "+f"(c[3])
                 : "r"(a[0]), "r"(a[1]), "r"(a[2]), "r"(a[3]), "r"(b[0]), "r"(b[1]));
}

// SMEM geometry: rows of 32 halves (64B) padded to 80B pitch -> conflict-free
// ldmatrix (8-row phase banks: r*20 mod 32 all distinct) and 16B-aligned cp.async.
constexpr int PITCH   = 80;
constexpr int SUBT    = 128 * PITCH;   // 10240 B per operand subtile
constexpr int STAGE   = 4 * SUBT;      // Ahi|Alo|Bhi|Blo = 40960 B
constexpr int SMEM_SZ = 2 * STAGE;     // double buffered = 81920 B

// ---------------------------------------------------------------------------
// fp16 split GEMM via mma.sync: C[m,n] = scale * sum_k A[m,k]*B[n,k]
//   A = Ahi+Alo, B = Bhi+Blo (hi/lo split of fp32), both K-major [rows, K].
//   NPASS=3: hi*hi + hi*lo + lo*hi  (error ~2^-22)
//   NPASS=2: hi*hi + hi*lo = Ahi * B exactly-per-term (error ~2^-11, random
//            sign cancellation; Alo neither staged nor read)
//   EPI=0: fp32 C.  EPI=1: hi/lo fp16 split C.
//   causal=1: skip tiles above diagonal.  kcap=1: K capped at bm0+128.
// ---------------------------------------------------------------------------
template <int EPI, int NPASS>
__global__ __launch_bounds__(256, 2)
void gemm_mma(const __half* __restrict__ Ahi, const __half* __restrict__ Alo,
              const __half* __restrict__ Bhi, const __half* __restrict__ Blo,
              float* __restrict__ Cf,
              __half* __restrict__ Chi, __half* __restrict__ Clo,
              int K, int lda, int ldb, int ldc,
              int zdiv, int bdiv,
              long long sA1, long long sA2, long long sB1, long long sB2,
              long long sC1, long long sC2,
              float scale, int causal, int kcap)
{
    const int bm0 = blockIdx.y * 128;
    const int bn0 = blockIdx.x * 128;
    if (causal && bn0 > bm0) return;

    const int z  = blockIdx.z;
    const int z2 = z / zdiv;
    const int z1 = z - z2 * zdiv;
    const __half* Ah = Ahi + z2 * sA2 + (long long)z1 * sA1;
    const __half* Al = Alo + z2 * sA2 + (long long)z1 * sA1;
    const __half* Bh = Bhi + z2 * sB2 + (long long)(z1 / bdiv) * sB1;
    const __half* Bl = Blo + z2 * sB2 + (long long)(z1 / bdiv) * sB1;
    const long long coff = z2 * sC2 + (long long)z1 * sC1;

    extern __shared__ char smem[];
    const unsigned sb = smem_u32(smem);
    const int tid  = threadIdx.x;
    const int lane = tid & 31;
    const int wid  = tid >> 5;
    const int wm   = wid & 3;     // 4 warp-rows x 32
    const int wn   = wid >> 2;    // 2 warp-cols x 64

    int Keff = K;
    if (kcap) { int c = bm0 + 128; if (c < Keff) Keff = c; }
    const int nk = Keff >> 5;     // KC = 32

    auto stage = [&](int si) {
        const unsigned base = sb + (si & 1) * STAGE;
        const int kc = si * 32;
        #pragma unroll
        for (int it = 0; it < 8; it++) {
            const int sub = it >> 1;                 // 0:Ahi 1:Alo 2:Bhi 3:Blo
            if (NPASS == 2 && sub == 1) continue;    // Alo unused in 2-pass
            const int w   = (tid + it * 256) & 511;
            const int row = w >> 2, seg = w & 3;     // 4 x 16B per 64B row
            const __half* src;
            if      (sub == 0) src = Ah + (long long)(bm0 + row) * lda + kc + seg * 8;
            else if (sub == 1) src = Al + (long long)(bm0 + row) * lda + kc + seg * 8;
            else if (sub == 2) src = Bh + (long long)(bn0 + row) * ldb + kc + seg * 8;
            else               src = Bl + (long long)(bn0 + row) * ldb + kc + seg * 8;
            cpa16(base + sub * SUBT + row * PITCH + seg * 16, src);
        }
    };

    float acc[2][8][4];
    #pragma unroll
    for (int i = 0; i < 2; i++)
        #pragma unroll
        for (int j = 0; j < 8; j++)
            #pragma unroll
            for (int e = 0; e < 4; e++) acc[i][j][e] = 0.0f;

    stage(0); cpa_commit();
    stage(1); cpa_commit();

    // ldmatrix lane address components (constant across chunks)
    const int arow = wm * 32 + (lane & 15);          // + mt*16
    const int asel = (lane >> 4);                    // 16B chunk within kstep
    const int brow = wn * 64 + (lane & 7) + ((lane >> 4) << 3);  // + pr*16
    const int bsel = (lane >> 3) & 1;

    for (int i = 0; i < nk; i++) {
        if (i + 1 < nk) cpa_wait1(); else cpa_wait0();
        __syncthreads();
        const unsigned base = sb + (i & 1) * STAGE;

        #pragma unroll
        for (int ks = 0; ks < 2; ks++) {
            unsigned ah[2][4], al[2][4];
            #pragma unroll
            for (int mt = 0; mt < 2; mt++) {
                const unsigned off = (arow + mt * 16) * PITCH + (ks * 2 + asel) * 16;
                ldsm4(ah[mt], base + off);
                if (NPASS == 3) ldsm4(al[mt], base + SUBT + off);
            }
            #pragma unroll
            for (int pr = 0; pr < 4; pr++) {
                unsigned bh[4], bl[4];
                const unsigned off = (brow + pr * 16) * PITCH + (ks * 2 + bsel) * 16;
                ldsm4(bh, base + 2 * SUBT + off);
                ldsm4(bl, base + 3 * SUBT + off);
                #pragma unroll
                for (int mt = 0; mt < 2; mt++)
                    #pragma unroll
                    for (int hf = 0; hf < 2; hf++) {
                        float* c = acc[mt][pr * 2 + hf];
                        mma16816(c, ah[mt], &bh[hf * 2]);
                        mma16816(c, ah[mt], &bl[hf * 2]);
                        if (NPASS == 3) mma16816(c, al[mt], &bh[hf * 2]);
                    }
            }
        }
        __syncthreads();
        if (i + 2 < nk) { stage(i + 2); cpa_commit(); }
    }

    // Epilogue: register accumulators -> global (float2 / half2 stores)
    const int er = bm0 + wm * 32 + (lane >> 2);
    const int ec = bn0 + wn * 64 + (lane & 3) * 2;
    #pragma unroll
    for (int mt = 0; mt < 2; mt++)
        #pragma unroll
        for (int nt = 0; nt < 8; nt++) {
            const float* c = acc[mt][nt];
            const int row = er + mt * 16;
            const int col = ec + nt * 8;
            const long long gi0 = coff + (long long)row * ldc + col;
            const long long gi1 = coff + (long long)(row + 8) * ldc + col;
            if (EPI == 0) {
                *(float2*)(Cf + gi0) = make_float2(c[0] * scale, c[1] * scale);
                *(float2*)(Cf + gi1) = make_float2(c[2] * scale, c[3] * scale);
            } else {
                float v0 = c[0] * scale, v1 = c[1] * scale;
                float v2 = c[2] * scale, v3 = c[3] * scale;
                __half h0 = __float2half(v0), h1 = __float2half(v1);
                __half h2 = __float2half(v2), h3 = __float2half(v3);
                *(__half2*)(Chi + gi0) = __halves2half2(h0, h1);
                *(__half2*)(Chi + gi1) = __halves2half2(h2, h3);
                *(__half2*)(Clo + gi0) = __halves2half2(
                    __float2half(v0 - __half2float(h0)),
                    __float2half(v1 - __half2float(h1)));
                *(__half2*)(Clo + gi1) = __halves2half2(
                    __float2half(v2 - __half2float(h2)),
                    __float2half(v3 - __half2float(h3)));
            }
        }
}

// ---------------------------------------------------------------------------
// Elementwise fp32 -> (hi, lo) fp16 split
// ---------------------------------------------------------------------------
__global__ __launch_bounds__(256)
void split_k(const float4* __restrict__ s, __half2* __restrict__ h2,
             __half2* __restrict__ l2, int n4)
{
    int i = blockIdx.x * 256 + threadIdx.x;
    if (i >= n4) return;
    float4 v = s[i];
    __half hx = __float2half(v.x), hy = __float2half(v.y);
    __half hz = __float2half(v.z), hw = __float2half(v.w);
    h2[2 * i]     = __halves2half2(hx, hy);
    h2[2 * i + 1] = __halves2half2(hz, hw);
    l2[2 * i]     = __halves2half2(__float2half(v.x - __half2float(hx)),
                                   __float2half(v.y - __half2float(hy)));
    l2[2 * i + 1] = __halves2half2(__float2half(v.z - __half2float(hz)),
                                   __float2half(v.w - __half2float(hw)));
}

// ---------------------------------------------------------------------------
// RoPE + split: reads fp32 [B,S,nh,HD], writes hi/lo fp16 same layout
// ---------------------------------------------------------------------------
__global__ __launch_bounds__(256)
void rope_split_k(const float* __restrict__ t, int nh,
                  const float* __restrict__ cs, const float* __restrict__ sn,
                  __half* __restrict__ hi, __half* __restrict__ lo)
{
    long long idx = (long long)blockIdx.x * 256 + threadIdx.x;
    const long long total = (long long)B_ * S_ * nh * (HD_ / 2);
    if (idx >= total) return;
    const int i = (int)(idx & 63);
    long long r = idx >> 6;
    const int h = (int)(r % nh); r /= nh;
    const int s = (int)(r % S_);
    const long long b = r / S_;

    const float c  = cs[s * 64 + i];
    const float si = sn[s * 64 + i];
    const long long off = (((b * S_ + s) * nh + h) * (long long)HD_) + 2 * i;
    const float t0 = t[off], t1 = t[off + 1];
    const float o0 = t0 * c - t1 * si;
    const float o1 = t0 * si + t1 * c;
    __half h0 = __float2half(o0);
    __half h1 = __float2half(o1);
    hi[off] = h0;     lo[off]     = __float2half(o0 - __half2float(h0));
    hi[off + 1] = h1; lo[off + 1] = __float2half(o1 - __half2float(h1));
}

// ---------------------------------------------------------------------------
// V transpose + split: vf32 [b,s,kv,d] -> vt hi/lo [b,kv,d,s]
// ---------------------------------------------------------------------------
__global__ __launch_bounds__(256)
void tsplit_v_k(const float* __restrict__ v,
                __half* __restrict__ hi, __half* __restrict__ lo)
{
    __shared__ float tile[32][33];
    const int bz = blockIdx.z;
    const int b = bz >> 3, kv = bz & 7;
    const int s0 = blockIdx.x * 32, d0 = blockIdx.y * 32;
    const int tx = threadIdx.x & 31, ty = threadIdx.x >> 5;

    #pragma unroll
    for (int j = 0; j < 4; j++) {
        int s = s0 + ty + j * 8;
        tile[ty + j * 8][tx] = v[((size_t)(b * S_ + s) * NKV_ + kv) * HD_ + d0 + tx];
    }
    __syncthreads();
    #pragma unroll
    for (int j = 0; j < 4; j++) {
        int d = d0 + ty + j * 8;
        float val = tile[tx][ty + j * 8];
        size_t o = ((size_t)(b * NKV_ + kv) * HD_ + d) * S_ + s0 + tx;
        __half h = __float2half(val);
        hi[o] = h;
        lo[o] = __float2half(val - __half2float(h));
    }
}

// ---------------------------------------------------------------------------
// Causal softmax, register-resident: ONE global read of the row (L <= 2048 =
// 256 thr x 8 regs), exp computed once, hi/lo fp16 out. Zero-fills only to the
// next 128-col boundary (= PV kcap limit).
// ---------------------------------------------------------------------------
__global__ __launch_bounds__(256)
void softmax_k(const float* __restrict__ sc,
               __half* __restrict__ phi, __half* __restrict__ plo)
{
    const long long row = blockIdx.x;
    const int q = (int)(row % S_);
    const float* p = sc + row * (long long)S_;
    __half* oh = phi + row * (long long)S_;
    __half* ol = plo + row * (long long)S_;
    const int L = q + 1;
    const int tid = threadIdx.x;
    __shared__ float red[8];

    float r[8];
    float m = -1e30f;
    #pragma unroll
    for (int j = 0; j < 8; j++) {
        const int i = tid + j * 256;
        r[j] = (i < L) ? p[i] : -1e30f;
        m = fmaxf(m, r[j]);
    }
    #pragma unroll
    for (int o = 16; o; o >>= 1) m = fmaxf(m, __shfl_xor_sync(0xffffffffu, m, o));
    if ((tid & 31) == 0) red[tid >> 5] = m;
    __syncthreads();
    m = red[0];
    #pragma unroll
    for (int i = 1; i < 8; i++) m = fmaxf(m, red[i]);
    __syncthreads();

    float s = 0.0f;
    #pragma unroll
    for (int j = 0; j < 8; j++) {
        const int i = tid + j * 256;
        r[j] = (i < L) ? expf(r[j] - m) : 0.0f;
        s += r[j];
    }
    #pragma unroll
    for (int o = 16; o; o >>= 1) s += __shfl_xor_sync(0xffffffffu, s, o);
    if ((tid & 31) == 0) red[tid >> 5] = s;
    __syncthreads();
    s = red[0];
    #pragma unroll
    for (int i = 1; i < 8; i++) s += red[i];

    const float inv = 1.0f / s;
    #pragma unroll
    for (int j = 0; j < 8; j++) {
        const int i = tid + j * 256;
        if (i < L) {
            const float e = r[j] * inv;
            __half h = __float2half(e);
            oh[i] = h;
            ol[i] = __float2half(e - __half2float(h));
        }
    }
    const int zend = ((q >> 7) + 1) << 7;   // next 128 boundary (= PV kcap limit)
    const __half z = __float2half(0.0f);
    for (int i = L + tid; i < zend; i += 256) { oh[i] = z; ol[i] = z; }
}

// ---------------------------------------------------------------------------
// Inputs (metadata order): x, wq, wk, wv, wo, freqs_cos, freqs_sin
// ---------------------------------------------------------------------------
extern "C" void kernel_launch(void* const* d_in, const int* in_sizes, int n_in,
                              void* d_out, int out_size)
{
    const float* x  = (const float*)d_in[0];
    const float* wq = (const float*)d_in[1];
    const float* wk = (const float*)d_in[2];
    const float* wv = (const float*)d_in[3];
    const float* wo = (const float*)d_in[4];
    const float* fc = (const float*)d_in[5];
    const float* fs = (const float*)d_in[6];
    float* out = (float*)d_out;

    __half *xhi, *xlo, *wqhi, *wqlo, *wkhi, *wklo, *wvhi, *wvlo, *wohi, *wolo;
    __half *qhi, *qlo, *khi, *klo, *vthi, *vtlo, *phi, *plo, *ahi, *alo;
    float *qf, *kf, *vf, *sp;
    cudaGetSymbolAddress((void**)&xhi,  g_xhi);  cudaGetSymbolAddress((void**)&xlo,  g_xlo);
    cudaGetSymbolAddress((void**)&wqhi, g_wqhi); cudaGetSymbolAddress((void**)&wqlo, g_wqlo);
    cudaGetSymbolAddress((void**)&wkhi, g_wkhi); cudaGetSymbolAddress((void**)&wklo, g_wklo);
    cudaGetSymbolAddress((void**)&wvhi, g_wvhi); cudaGetSymbolAddress((void**)&wvlo, g_wvlo);
    cudaGetSymbolAddress((void**)&wohi, g_wohi); cudaGetSymbolAddress((void**)&wolo, g_wolo);
    cudaGetSymbolAddress((void**)&qf, g_qf);
    cudaGetSymbolAddress((void**)&kf, g_kf);
    cudaGetSymbolAddress((void**)&vf, g_vf);
    cudaGetSymbolAddress((void**)&qhi, g_qhi);   cudaGetSymbolAddress((void**)&qlo, g_qlo);
    cudaGetSymbolAddress((void**)&khi, g_khi);   cudaGetSymbolAddress((void**)&klo, g_klo);
    cudaGetSymbolAddress((void**)&vthi, g_vthi); cudaGetSymbolAddress((void**)&vtlo, g_vtlo);
    cudaGetSymbolAddress((void**)&sp, g_sc);
    cudaGetSymbolAddress((void**)&phi, g_phi);   cudaGetSymbolAddress((void**)&plo, g_plo);
    cudaGetSymbolAddress((void**)&ahi, g_ahi);   cudaGetSymbolAddress((void**)&alo, g_alo);

    cudaFuncSetAttribute(gemm_mma<0,2>, cudaFuncAttributeMaxDynamicSharedMemorySize, SMEM_SZ);
    cudaFuncSetAttribute(gemm_mma<0,3>, cudaFuncAttributeMaxDynamicSharedMemorySize, SMEM_SZ);
    cudaFuncSetAttribute(gemm_mma<1,3>, cudaFuncAttributeMaxDynamicSharedMemorySize, SMEM_SZ);

    const float scale = 0.08838834764831845f;  // 1/sqrt(128)

    // 1) split inputs into fp16 hi/lo
    split_k<<<16384, 256>>>((const float4*)x,  (__half2*)xhi,  (__half2*)xlo,  4194304);
    split_k<<<16384, 256>>>((const float4*)wq, (__half2*)wqhi, (__half2*)wqlo, 4194304);
    split_k<<<4096,  256>>>((const float4*)wk, (__half2*)wkhi, (__half2*)wklo, 1048576);
    split_k<<<4096,  256>>>((const float4*)wv, (__half2*)wvhi, (__half2*)wvlo, 1048576);
    split_k<<<16384, 256>>>((const float4*)wo, (__half2*)wohi, (__half2*)wolo, 4194304);

    // 2) projections (fp32 out, 2-pass fp16)
    gemm_mma<0,2><<<dim3(32, 32, 1), 256, SMEM_SZ>>>(
        xhi, xlo, wqhi, wqlo, qf, nullptr, nullptr,
        DIM_, DIM_, DIM_, DIM_, 1, 1, 0, 0, 0, 0, 0, 0, 1.0f, 0, 0);
    gemm_mma<0,2><<<dim3(8, 32, 1), 256, SMEM_SZ>>>(
        xhi, xlo, wkhi, wklo, kf, nullptr, nullptr,
        DIM_, DIM_, DIM_, NKV_ * HD_, 1, 1, 0, 0, 0, 0, 0, 0, 1.0f, 0, 0);
    gemm_mma<0,2><<<dim3(8, 32, 1), 256, SMEM_SZ>>>(
        xhi, xlo, wvhi, wvlo, vf, nullptr, nullptr,
        DIM_, DIM_, DIM_, NKV_ * HD_, 1, 1, 0, 0, 0, 0, 0, 0, 1.0f, 0, 0);

    // 3) RoPE + split (q, k); V transpose + split
    rope_split_k<<<32768, 256>>>(qf, NH_, fc, fs, qhi, qlo);
    rope_split_k<<<8192, 256>>>(kf, NKV_, fc, fs, khi, klo);
    tsplit_v_k<<<dim3(S_ / 32, HD_ / 32, B_ * NKV_), 256>>>(vf, vthi, vtlo);

    // 4) scores = scale * Q K^T  (causal tile skip, 3-pass fp16)
    gemm_mma<0,3><<<dim3(16, 16, B_ * NH_), 256, SMEM_SZ>>>(
        qhi, qlo, khi, klo, sp, nullptr, nullptr,
        HD_, NH_ * HD_, NKV_ * HD_, S_,
        NH_, 4,
        (long long)HD_, (long long)S_ * NH_ * HD_,
        (long long)HD_, (long long)S_ * NKV_ * HD_,
        (long long)S_ * S_, (long long)NH_ * S_ * S_,
        scale, 1, 0);

    // 5) softmax -> split probs (single-read, register-resident)
    softmax_k<<<B_ * NH_ * S_, 256>>>(sp, phi, plo);

    // 6) attn = P V  (K capped causally; split epilogue, 3-pass fp16)
    gemm_mma<1,3><<<dim3(1, 16, B_ * NH_), 256, SMEM_SZ>>>(
        phi, plo, vthi, vtlo, nullptr, ahi, alo,
        S_, S_, S_, NH_ * HD_,
        NH_, 4,
        (long long)S_ * S_, (long long)NH_ * S_ * S_,
        (long long)HD_ * S_, (long long)NKV_ * HD_ * S_,
        (long long)HD_, (long long)S_ * NH_ * HD_,
        1.0f, 0, 1);

    // 7) output projection (2-pass fp16)
    gemm_mma<0,2><<<dim3(32, 32, 1), 256, SMEM_SZ>>>(
        ahi, alo, wohi, wolo, out, nullptr, nullptr,
        DIM_, DIM_, DIM_, DIM_, 1, 1, 0, 0, 0, 0, 0, 0, 1.0f, 0, 0);
}

// round 9
// speedup vs baseline: 1.7933x; 1.0506x over previous
#include <cuda_runtime.h>
#include <cuda_fp16.h>
#include <math.h>

// Problem constants
constexpr int B_   = 2;
constexpr int S_   = 2048;
constexpr int DIM_ = 4096;
constexpr int NH_  = 32;
constexpr int NKV_ = 8;
constexpr int HD_  = 128;

// ---------------------------------------------------------------------------
// Scratch (module-scope device arrays; allocation-free at launch time)
// xlo / plo / alo are gone: nothing reads them (all consumers are 2-pass on A).
// ---------------------------------------------------------------------------
__device__ __half g_xhi[16777216];                       // x hi (lo unused)
__device__ __half g_wqhi[16777216], g_wqlo[16777216];
__device__ __half g_wkhi[4194304],  g_wklo[4194304];
__device__ __half g_wvhi[4194304],  g_wvlo[4194304];
__device__ __half g_wohi[16777216], g_wolo[16777216];
__device__ float  g_qf[16777216];                        // q fp32 (pre-rope)
__device__ float  g_kf[4194304];
__device__ float  g_vf[4194304];
__device__ __half g_qhi[16777216], g_qlo[16777216];      // post-rope split (QK is 3-pass)
__device__ __half g_khi[4194304],  g_klo[4194304];
__device__ __half g_vthi[4194304], g_vtlo[4194304];      // V transposed [b,kv,d,s]
__device__ float  g_sc[268435456];                       // scores fp32 [b,h,q,k]
__device__ __half g_phi[268435456];                      // probs hi (PV is 2-pass)
__device__ __half g_ahi[16777216];                       // attn hi (out-proj 2-pass)

// ---------------------------------------------------------------------------
// PTX helpers — sm_80-era only (compute_103 virtual arch: NO tcgen05)
// ---------------------------------------------------------------------------
__device__ __forceinline__ unsigned smem_u32(const void* p) {
    return (unsigned)__cvta_generic_to_shared(p);
}
__device__ __forceinline__ void cpa16(unsigned dst, const void* src) {
    asm volatile("cp.async.cg.shared.global [%0], [%1], 16;" :: "r"(dst), "l"(src) : "memory");
}
__device__ __forceinline__ void cpa_commit() {
    asm volatile("cp.async.commit_group;" ::: "memory");
}
__device__ __forceinline__ void cpa_wait1() {
    asm volatile("cp.async.wait_group 1;" ::: "memory");
}
__device__ __forceinline__ void cpa_wait0() {
    asm volatile("cp.async.wait_group 0;" ::: "memory");
}
__device__ __forceinline__ void ldsm4(unsigned* r, unsigned a) {
    asm volatile("ldmatrix.sync.aligned.m8n8.x4.shared.b16 {%0,%1,%2,%3}, [%4];"
                 : "=r"(r[0]), "=r"(r[1]), "=r"(r[2]), "=r"(r[3]) : "r"(a));
}
__device__ __forceinline__ void mma16816(float* c, const unsigned* a, const unsigned* b) {
    asm volatile("mma.sync.aligned.m16n8k16.row.col.f32.f16.f16.f32 "
                 "{%0,%1,%2,%3}, {%4,%5,%6,%7}, {%8,%9}, {%0,%1,%2,%3};"
                 : "+f"(c[0]), "+f"(c[1]), "+f"(c[2]), "+f"(c[3])
                 : "r"(a[0]), "r"(a[1]), "r"(a[2]), "r"(a[3]), "r"(b[0]), "r"(b[1]));
}

// SMEM geometry: rows of 32 halves (64B) padded to 80B pitch -> conflict-free
// ldmatrix (8-row phase banks: r*20 mod 32 all distinct) and 16B-aligned cp.async.
constexpr int PITCH   = 80;
constexpr int SUBT    = 128 * PITCH;   // 10240 B per operand subtile
constexpr int STAGE   = 4 * SUBT;      // Ahi|Alo|Bhi|Blo = 40960 B
constexpr int SMEM_SZ = 2 * STAGE;     // double buffered = 81920 B

// ---------------------------------------------------------------------------
// fp16 split GEMM via mma.sync: C[m,n] = scale * sum_k A[m,k]*B[n,k]
//   A = Ahi+Alo, B = Bhi+Blo (hi/lo split of fp32), both K-major [rows, K].
//   NPASS=3: hi*hi + hi*lo + lo*hi  (error ~2^-22)
//   NPASS=2: hi*hi + hi*lo = Ahi * B exactly-per-term (error ~2^-11, random
//            sign cancellation; Alo neither staged nor read)
//   EPI=0: fp32 C.  EPI=1: fp16 hi-only C.
//   causal=1: skip tiles above diagonal.  kcap=1: K capped at bm0+128.
// ---------------------------------------------------------------------------
template <int EPI, int NPASS>
__global__ __launch_bounds__(256, 2)
void gemm_mma(const __half* __restrict__ Ahi, const __half* __restrict__ Alo,
              const __half* __restrict__ Bhi, const __half* __restrict__ Blo,
              float* __restrict__ Cf, __half* __restrict__ Chi,
              int K, int lda, int ldb, int ldc,
              int zdiv, int bdiv,
              long long sA1, long long sA2, long long sB1, long long sB2,
              long long sC1, long long sC2,
              float scale, int causal, int kcap)
{
    const int bm0 = blockIdx.y * 128;
    const int bn0 = blockIdx.x * 128;
    if (causal && bn0 > bm0) return;

    const int z  = blockIdx.z;
    const int z2 = z / zdiv;
    const int z1 = z - z2 * zdiv;
    const __half* Ah = Ahi + z2 * sA2 + (long long)z1 * sA1;
    const __half* Al = (NPASS == 3) ? Alo + z2 * sA2 + (long long)z1 * sA1 : nullptr;
    const __half* Bh = Bhi + z2 * sB2 + (long long)(z1 / bdiv) * sB1;
    const __half* Bl = Blo + z2 * sB2 + (long long)(z1 / bdiv) * sB1;
    const long long coff = z2 * sC2 + (long long)z1 * sC1;

    extern __shared__ char smem[];
    const unsigned sb = smem_u32(smem);
    const int tid  = threadIdx.x;
    const int lane = tid & 31;
    const int wid  = tid >> 5;
    const int wm   = wid & 3;     // 4 warp-rows x 32
    const int wn   = wid >> 2;    // 2 warp-cols x 64

    int Keff = K;
    if (kcap) { int c = bm0 + 128; if (c < Keff) Keff = c; }
    const int nk = Keff >> 5;     // KC = 32

    auto stage = [&](int si) {
        const unsigned base = sb + (si & 1) * STAGE;
        const int kc = si * 32;
        #pragma unroll
        for (int it = 0; it < 8; it++) {
            const int sub = it >> 1;                 // 0:Ahi 1:Alo 2:Bhi 3:Blo
            if (NPASS == 2 && sub == 1) continue;    // Alo unused in 2-pass
            const int w   = (tid + it * 256) & 511;
            const int row = w >> 2, seg = w & 3;     // 4 x 16B per 64B row
            const __half* src;
            if      (sub == 0) src = Ah + (long long)(bm0 + row) * lda + kc + seg * 8;
            else if (sub == 1) src = Al + (long long)(bm0 + row) * lda + kc + seg * 8;
            else if (sub == 2) src = Bh + (long long)(bn0 + row) * ldb + kc + seg * 8;
            else               src = Bl + (long long)(bn0 + row) * ldb + kc + seg * 8;
            cpa16(base + sub * SUBT + row * PITCH + seg * 16, src);
        }
    };

    float acc[2][8][4];
    #pragma unroll
    for (int i = 0; i < 2; i++)
        #pragma unroll
        for (int j = 0; j < 8; j++)
            #pragma unroll
            for (int e = 0; e < 4; e++) acc[i][j][e] = 0.0f;

    stage(0); cpa_commit();
    stage(1); cpa_commit();

    // ldmatrix lane address components (constant across chunks)
    const int arow = wm * 32 + (lane & 15);          // + mt*16
    const int asel = (lane >> 4);                    // 16B chunk within kstep
    const int brow = wn * 64 + (lane & 7) + ((lane >> 4) << 3);  // + pr*16
    const int bsel = (lane >> 3) & 1;

    for (int i = 0; i < nk; i++) {
        if (i + 1 < nk) cpa_wait1(); else cpa_wait0();
        __syncthreads();
        const unsigned base = sb + (i & 1) * STAGE;

        #pragma unroll
        for (int ks = 0; ks < 2; ks++) {
            unsigned ah[2][4], al[2][4];
            #pragma unroll
            for (int mt = 0; mt < 2; mt++) {
                const unsigned off = (arow + mt * 16) * PITCH + (ks * 2 + asel) * 16;
                ldsm4(ah[mt], base + off);
                if (NPASS == 3) ldsm4(al[mt], base + SUBT + off);
            }
            #pragma unroll
            for (int pr = 0; pr < 4; pr++) {
                unsigned bh[4], bl[4];
                const unsigned off = (brow + pr * 16) * PITCH + (ks * 2 + bsel) * 16;
                ldsm4(bh, base + 2 * SUBT + off);
                ldsm4(bl, base + 3 * SUBT + off);
                #pragma unroll
                for (int mt = 0; mt < 2; mt++)
                    #pragma unroll
                    for (int hf = 0; hf < 2; hf++) {
                        float* c = acc[mt][pr * 2 + hf];
                        mma16816(c, ah[mt], &bh[hf * 2]);
                        mma16816(c, ah[mt], &bl[hf * 2]);
                        if (NPASS == 3) mma16816(c, al[mt], &bh[hf * 2]);
                    }
            }
        }
        __syncthreads();
        if (i + 2 < nk) { stage(i + 2); cpa_commit(); }
    }

    // Epilogue: register accumulators -> global (float2 / half2 stores)
    const int er = bm0 + wm * 32 + (lane >> 2);
    const int ec = bn0 + wn * 64 + (lane & 3) * 2;
    #pragma unroll
    for (int mt = 0; mt < 2; mt++)
        #pragma unroll
        for (int nt = 0; nt < 8; nt++) {
            const float* c = acc[mt][nt];
            const int row = er + mt * 16;
            const int col = ec + nt * 8;
            const long long gi0 = coff + (long long)row * ldc + col;
            const long long gi1 = coff + (long long)(row + 8) * ldc + col;
            if (EPI == 0) {
                *(float2*)(Cf + gi0) = make_float2(c[0] * scale, c[1] * scale);
                *(float2*)(Cf + gi1) = make_float2(c[2] * scale, c[3] * scale);
            } else {
                *(__half2*)(Chi + gi0) = __halves2half2(
                    __float2half(c[0] * scale), __float2half(c[1] * scale));
                *(__half2*)(Chi + gi1) = __halves2half2(
                    __float2half(c[2] * scale), __float2half(c[3] * scale));
            }
        }
}

// ---------------------------------------------------------------------------
// Elementwise fp32 -> fp16 split.  LO=1: write (hi, lo);  LO=0: hi only.
// ---------------------------------------------------------------------------
template <int LO>
__global__ __launch_bounds__(256)
void split_k(const float4* __restrict__ s, __half2* __restrict__ h2,
             __half2* __restrict__ l2, int n4)
{
    int i = blockIdx.x * 256 + threadIdx.x;
    if (i >= n4) return;
    float4 v = s[i];
    __half hx = __float2half(v.x), hy = __float2half(v.y);
    __half hz = __float2half(v.z), hw = __float2half(v.w);
    h2[2 * i]     = __halves2half2(hx, hy);
    h2[2 * i + 1] = __halves2half2(hz, hw);
    if (LO) {
        l2[2 * i]     = __halves2half2(__float2half(v.x - __half2float(hx)),
                                       __float2half(v.y - __half2float(hy)));
        l2[2 * i + 1] = __halves2half2(__float2half(v.z - __half2float(hz)),
                                       __float2half(v.w - __half2float(hw)));
    }
}

// ---------------------------------------------------------------------------
// RoPE + split: reads fp32 [B,S,nh,HD], writes hi/lo fp16 same layout
// ---------------------------------------------------------------------------
__global__ __launch_bounds__(256)
void rope_split_k(const float* __restrict__ t, int nh,
                  const float* __restrict__ cs, const float* __restrict__ sn,
                  __half* __restrict__ hi, __half* __restrict__ lo)
{
    long long idx = (long long)blockIdx.x * 256 + threadIdx.x;
    const long long total = (long long)B_ * S_ * nh * (HD_ / 2);
    if (idx >= total) return;
    const int i = (int)(idx & 63);
    long long r = idx >> 6;
    const int h = (int)(r % nh); r /= nh;
    const int s = (int)(r % S_);
    const long long b = r / S_;

    const float c  = cs[s * 64 + i];
    const float si = sn[s * 64 + i];
    const long long off = (((b * S_ + s) * nh + h) * (long long)HD_) + 2 * i;
    const float t0 = t[off], t1 = t[off + 1];
    const float o0 = t0 * c - t1 * si;
    const float o1 = t0 * si + t1 * c;
    __half h0 = __float2half(o0);
    __half h1 = __float2half(o1);
    hi[off] = h0;     lo[off]     = __float2half(o0 - __half2float(h0));
    hi[off + 1] = h1; lo[off + 1] = __float2half(o1 - __half2float(h1));
}

// ---------------------------------------------------------------------------
// V transpose + split: vf32 [b,s,kv,d] -> vt hi/lo [b,kv,d,s]
// ---------------------------------------------------------------------------
__global__ __launch_bounds__(256)
void tsplit_v_k(const float* __restrict__ v,
                __half* __restrict__ hi, __half* __restrict__ lo)
{
    __shared__ float tile[32][33];
    const int bz = blockIdx.z;
    const int b = bz >> 3, kv = bz & 7;
    const int s0 = blockIdx.x * 32, d0 = blockIdx.y * 32;
    const int tx = threadIdx.x & 31, ty = threadIdx.x >> 5;

    #pragma unroll
    for (int j = 0; j < 4; j++) {
        int s = s0 + ty + j * 8;
        tile[ty + j * 8][tx] = v[((size_t)(b * S_ + s) * NKV_ + kv) * HD_ + d0 + tx];
    }
    __syncthreads();
    #pragma unroll
    for (int j = 0; j < 4; j++) {
        int d = d0 + ty + j * 8;
        float val = tile[tx][ty + j * 8];
        size_t o = ((size_t)(b * NKV_ + kv) * HD_ + d) * S_ + s0 + tx;
        __half h = __float2half(val);
        hi[o] = h;
        lo[o] = __float2half(val - __half2float(h));
    }
}

// ---------------------------------------------------------------------------
// Causal softmax, register-resident: ONE global read of the row (L <= 2048 =
// 256 thr x 8 regs), exp computed once, fp16 hi-only out (PV is 2-pass on A).
// Zero-fills only to the next 128-col boundary (= PV kcap limit).
// ---------------------------------------------------------------------------
__global__ __launch_bounds__(256)
void softmax_k(const float* __restrict__ sc, __half* __restrict__ phi)
{
    const long long row = blockIdx.x;
    const int q = (int)(row % S_);
    const float* p = sc + row * (long long)S_;
    __half* oh = phi + row * (long long)S_;
    const int L = q + 1;
    const int tid = threadIdx.x;
    __shared__ float red[8];

    float r[8];
    float m = -1e30f;
    #pragma unroll
    for (int j = 0; j < 8; j++) {
        const int i = tid + j * 256;
        r[j] = (i < L) ? p[i] : -1e30f;
        m = fmaxf(m, r[j]);
    }
    #pragma unroll
    for (int o = 16; o; o >>= 1) m = fmaxf(m, __shfl_xor_sync(0xffffffffu, m, o));
    if ((tid & 31) == 0) red[tid >> 5] = m;
    __syncthreads();
    m = red[0];
    #pragma unroll
    for (int i = 1; i < 8; i++) m = fmaxf(m, red[i]);
    __syncthreads();

    float s = 0.0f;
    #pragma unroll
    for (int j = 0; j < 8; j++) {
        const int i = tid + j * 256;
        r[j] = (i < L) ? expf(r[j] - m) : 0.0f;
        s += r[j];
    }
    #pragma unroll
    for (int o = 16; o; o >>= 1) s += __shfl_xor_sync(0xffffffffu, s, o);
    if ((tid & 31) == 0) red[tid >> 5] = s;
    __syncthreads();
    s = red[0];
    #pragma unroll
    for (int i = 1; i < 8; i++) s += red[i];

    const float inv = 1.0f / s;
    #pragma unroll
    for (int j = 0; j < 8; j++) {
        const int i = tid + j * 256;
        if (i < L) oh[i] = __float2half(r[j] * inv);
    }
    const int zend = ((q >> 7) + 1) << 7;   // next 128 boundary (= PV kcap limit)
    const __half z = __float2half(0.0f);
    for (int i = L + tid; i < zend; i += 256) oh[i] = z;
}

// ---------------------------------------------------------------------------
// Inputs (metadata order): x, wq, wk, wv, wo, freqs_cos, freqs_sin
// ---------------------------------------------------------------------------
extern "C" void kernel_launch(void* const* d_in, const int* in_sizes, int n_in,
                              void* d_out, int out_size)
{
    const float* x  = (const float*)d_in[0];
    const float* wq = (const float*)d_in[1];
    const float* wk = (const float*)d_in[2];
    const float* wv = (const float*)d_in[3];
    const float* wo = (const float*)d_in[4];
    const float* fc = (const float*)d_in[5];
    const float* fs = (const float*)d_in[6];
    float* out = (float*)d_out;

    __half *xhi, *wqhi, *wqlo, *wkhi, *wklo, *wvhi, *wvlo, *wohi, *wolo;
    __half *qhi, *qlo, *khi, *klo, *vthi, *vtlo, *phi, *ahi;
    float *qf, *kf, *vf, *sp;
    cudaGetSymbolAddress((void**)&xhi,  g_xhi);
    cudaGetSymbolAddress((void**)&wqhi, g_wqhi); cudaGetSymbolAddress((void**)&wqlo, g_wqlo);
    cudaGetSymbolAddress((void**)&wkhi, g_wkhi); cudaGetSymbolAddress((void**)&wklo, g_wklo);
    cudaGetSymbolAddress((void**)&wvhi, g_wvhi); cudaGetSymbolAddress((void**)&wvlo, g_wvlo);
    cudaGetSymbolAddress((void**)&wohi, g_wohi); cudaGetSymbolAddress((void**)&wolo, g_wolo);
    cudaGetSymbolAddress((void**)&qf, g_qf);
    cudaGetSymbolAddress((void**)&kf, g_kf);
    cudaGetSymbolAddress((void**)&vf, g_vf);
    cudaGetSymbolAddress((void**)&qhi, g_qhi);   cudaGetSymbolAddress((void**)&qlo, g_qlo);
    cudaGetSymbolAddress((void**)&khi, g_khi);   cudaGetSymbolAddress((void**)&klo, g_klo);
    cudaGetSymbolAddress((void**)&vthi, g_vthi); cudaGetSymbolAddress((void**)&vtlo, g_vtlo);
    cudaGetSymbolAddress((void**)&sp, g_sc);
    cudaGetSymbolAddress((void**)&phi, g_phi);
    cudaGetSymbolAddress((void**)&ahi, g_ahi);

    cudaFuncSetAttribute(gemm_mma<0,2>, cudaFuncAttributeMaxDynamicSharedMemorySize, SMEM_SZ);
    cudaFuncSetAttribute(gemm_mma<0,3>, cudaFuncAttributeMaxDynamicSharedMemorySize, SMEM_SZ);
    cudaFuncSetAttribute(gemm_mma<1,2>, cudaFuncAttributeMaxDynamicSharedMemorySize, SMEM_SZ);

    const float scale = 0.08838834764831845f;  // 1/sqrt(128)

    // 1) split inputs into fp16 hi/lo (x: hi only — lo is never read)
    split_k<0><<<16384, 256>>>((const float4*)x,  (__half2*)xhi,  nullptr,        4194304);
    split_k<1><<<16384, 256>>>((const float4*)wq, (__half2*)wqhi, (__half2*)wqlo, 4194304);
    split_k<1><<<4096,  256>>>((const float4*)wk, (__half2*)wkhi, (__half2*)wklo, 1048576);
    split_k<1><<<4096,  256>>>((const float4*)wv, (__half2*)wvhi, (__half2*)wvlo, 1048576);
    split_k<1><<<16384, 256>>>((const float4*)wo, (__half2*)wohi, (__half2*)wolo, 4194304);

    // 2) projections (fp32 out, 2-pass fp16)
    gemm_mma<0,2><<<dim3(32, 32, 1), 256, SMEM_SZ>>>(
        xhi, nullptr, wqhi, wqlo, qf, nullptr,
        DIM_, DIM_, DIM_, DIM_, 1, 1, 0, 0, 0, 0, 0, 0, 1.0f, 0, 0);
    gemm_mma<0,2><<<dim3(8, 32, 1), 256, SMEM_SZ>>>(
        xhi, nullptr, wkhi, wklo, kf, nullptr,
        DIM_, DIM_, DIM_, NKV_ * HD_, 1, 1, 0, 0, 0, 0, 0, 0, 1.0f, 0, 0);
    gemm_mma<0,2><<<dim3(8, 32, 1), 256, SMEM_SZ>>>(
        xhi, nullptr, wvhi, wvlo, vf, nullptr,
        DIM_, DIM_, DIM_, NKV_ * HD_, 1, 1, 0, 0, 0, 0, 0, 0, 1.0f, 0, 0);

    // 3) RoPE + split (q, k keep hi/lo — QK is 3-pass); V transpose + split
    rope_split_k<<<32768, 256>>>(qf, NH_, fc, fs, qhi, qlo);
    rope_split_k<<<8192, 256>>>(kf, NKV_, fc, fs, khi, klo);
    tsplit_v_k<<<dim3(S_ / 32, HD_ / 32, B_ * NKV_), 256>>>(vf, vthi, vtlo);

    // 4) scores = scale * Q K^T  (causal tile skip, 3-pass fp16)
    gemm_mma<0,3><<<dim3(16, 16, B_ * NH_), 256, SMEM_SZ>>>(
        qhi, qlo, khi, klo, sp, nullptr,
        HD_, NH_ * HD_, NKV_ * HD_, S_,
        NH_, 4,
        (long long)HD_, (long long)S_ * NH_ * HD_,
        (long long)HD_, (long long)S_ * NKV_ * HD_,
        (long long)S_ * S_, (long long)NH_ * S_ * S_,
        scale, 1, 0);

    // 5) softmax -> probs hi only (single-read, register-resident)
    softmax_k<<<B_ * NH_ * S_, 256>>>(sp, phi);

    // 6) attn = P V  (K capped causally; 2-pass: Phi*(Vhi+Vlo); hi-only out)
    gemm_mma<1,2><<<dim3(1, 16, B_ * NH_), 256, SMEM_SZ>>>(
        phi, nullptr, vthi, vtlo, nullptr, ahi,
        S_, S_, S_, NH_ * HD_,
        NH_, 4,
        (long long)S_ * S_, (long long)NH_ * S_ * S_,
        (long long)HD_ * S_, (long long)NKV_ * HD_ * S_,
        (long long)HD_, (long long)S_ * NH_ * HD_,
        1.0f, 0, 1);

    // 7) output projection (2-pass fp16, reads ahi only)
    gemm_mma<0,2><<<dim3(32, 32, 1), 256, SMEM_SZ>>>(
        ahi, nullptr, wohi, wolo, out, nullptr,
        DIM_, DIM_, DIM_, DIM_, 1, 1, 0, 0, 0, 0, 0, 0, 1.0f, 0, 0);
}

// round 10
// speedup vs baseline: 1.8608x; 1.0376x over previous
#include <cuda_runtime.h>
#include <cuda_fp16.h>
#include <math.h>

// Problem constants
constexpr int B_   = 2;
constexpr int S_   = 2048;
constexpr int DIM_ = 4096;
constexpr int NH_  = 32;
constexpr int NKV_ = 8;
constexpr int HD_  = 128;

// ---------------------------------------------------------------------------
// Scratch (module-scope device arrays; allocation-free at launch time)
// ---------------------------------------------------------------------------
__device__ __half g_xhi[16777216];                       // x hi (lo unused)
__device__ __half g_wqhi[16777216], g_wqlo[16777216];
__device__ __half g_wkhi[4194304],  g_wklo[4194304];
__device__ __half g_wvhi[4194304],  g_wvlo[4194304];
__device__ __half g_wohi[16777216], g_wolo[16777216];
__device__ float  g_vf[4194304];                         // v fp32 (pre-transpose)
__device__ __half g_qhi[16777216];                       // q hi post-rope (QK 2-pass)
__device__ __half g_khi[4194304],  g_klo[4194304];       // k hi/lo post-rope
__device__ __half g_vthi[4194304], g_vtlo[4194304];      // V transposed [b,kv,d,s]
__device__ float  g_sc[268435456];                       // scores fp32 [b,h,q,k]
__device__ __half g_phi[268435456];                      // probs hi (PV is 2-pass)
__device__ __half g_ahi[16777216];                       // attn hi (out-proj 2-pass)

// ---------------------------------------------------------------------------
// PTX helpers — sm_80-era only (compute_103 virtual arch: NO tcgen05)
// ---------------------------------------------------------------------------
__device__ __forceinline__ unsigned smem_u32(const void* p) {
    return (unsigned)__cvta_generic_to_shared(p);
}
__device__ __forceinline__ void cpa16(unsigned dst, const void* src) {
    asm volatile("cp.async.cg.shared.global [%0], [%1], 16;" :: "r"(dst), "l"(src) : "memory");
}
__device__ __forceinline__ void cpa_commit() {
    asm volatile("cp.async.commit_group;" ::: "memory");
}
__device__ __forceinline__ void cpa_wait1() {
    asm volatile("cp.async.wait_group 1;" ::: "memory");
}
__device__ __forceinline__ void cpa_wait0() {
    asm volatile("cp.async.wait_group 0;" ::: "memory");
}
__device__ __forceinline__ void ldsm4(unsigned* r, unsigned a) {
    asm volatile("ldmatrix.sync.aligned.m8n8.x4.shared.b16 {%0,%1,%2,%3}, [%4];"
                 : "=r"(r[0]), "=r"(r[1]), "=r"(r[2]), "=r"(r[3]) : "r"(a));
}
__device__ __forceinline__ void mma16816(float* c, const unsigned* a, const unsigned* b) {
    asm volatile("mma.sync.aligned.m16n8k16.row.col.f32.f16.f16.f32 "
                 "{%0,%1,%2,%3}, {%4,%5,%6,%7}, {%8,%9}, {%0,%1,%2,%3};"
                 : "+f"(c[0]), "+f"(c[1]), "+f"(c[2]), "+f"(c[3])
                 : "r"(a[0]), "r"(a[1]), "r"(a[2]), "r"(a[3]), "r"(b[0]), "r"(b[1]));
}

// SMEM geometry: rows of 32 halves (64B) padded to 80B pitch -> conflict-free
// ldmatrix (8-row phase banks: r*20 mod 32 all distinct) and 16B-aligned cp.async.
constexpr int PITCH   = 80;
constexpr int SUBT    = 128 * PITCH;   // 10240 B per operand subtile
constexpr int STAGE   = 4 * SUBT;      // Ahi|Alo|Bhi|Blo = 40960 B
constexpr int SMEM_SZ = 2 * STAGE;     // double buffered = 81920 B

// ---------------------------------------------------------------------------
// fp16 split GEMM via mma.sync: C[m,n] = scale * sum_k A[m,k]*B[n,k]
//   NPASS=3: hi*hi + hi*lo + lo*hi.  NPASS=2: hi*hi + hi*lo = Ahi*B (Alo dead).
//   EPI=0: fp32 C.          EPI=1: fp16 hi-only C.
//   EPI=2: RoPE -> fp16 hi. EPI=3: RoPE -> fp16 hi/lo.
//     (RoPE uses the fact that each epilogue thread holds the adjacent
//      even/odd column pair; i = (col&127)>>1, s = row & (S-1).)
//   causal=1: skip tiles above diagonal.  kcap=1: K capped at bm0+128.
// ---------------------------------------------------------------------------
template <int EPI, int NPASS>
__global__ __launch_bounds__(256, 2)
void gemm_mma(const __half* __restrict__ Ahi, const __half* __restrict__ Alo,
              const __half* __restrict__ Bhi, const __half* __restrict__ Blo,
              float* __restrict__ Cf, __half* __restrict__ Chi, __half* __restrict__ Clo,
              const float* __restrict__ cs, const float* __restrict__ sn,
              int K, int lda, int ldb, int ldc,
              int zdiv, int bdiv,
              long long sA1, long long sA2, long long sB1, long long sB2,
              long long sC1, long long sC2,
              float scale, int causal, int kcap)
{
    const int bm0 = blockIdx.y * 128;
    const int bn0 = blockIdx.x * 128;
    if (causal && bn0 > bm0) return;

    const int z  = blockIdx.z;
    const int z2 = z / zdiv;
    const int z1 = z - z2 * zdiv;
    const __half* Ah = Ahi + z2 * sA2 + (long long)z1 * sA1;
    const __half* Al = (NPASS == 3) ? Alo + z2 * sA2 + (long long)z1 * sA1 : nullptr;
    const __half* Bh = Bhi + z2 * sB2 + (long long)(z1 / bdiv) * sB1;
    const __half* Bl = Blo + z2 * sB2 + (long long)(z1 / bdiv) * sB1;
    const long long coff = z2 * sC2 + (long long)z1 * sC1;

    extern __shared__ char smem[];
    const unsigned sb = smem_u32(smem);
    const int tid  = threadIdx.x;
    const int lane = tid & 31;
    const int wid  = tid >> 5;
    const int wm   = wid & 3;     // 4 warp-rows x 32
    const int wn   = wid >> 2;    // 2 warp-cols x 64

    int Keff = K;
    if (kcap) { int c = bm0 + 128; if (c < Keff) Keff = c; }
    const int nk = Keff >> 5;     // KC = 32

    auto stage = [&](int si) {
        const unsigned base = sb + (si & 1) * STAGE;
        const int kc = si * 32;
        #pragma unroll
        for (int it = 0; it < 8; it++) {
            const int sub = it >> 1;                 // 0:Ahi 1:Alo 2:Bhi 3:Blo
            if (NPASS == 2 && sub == 1) continue;    // Alo unused in 2-pass
            const int w   = (tid + it * 256) & 511;
            const int row = w >> 2, seg = w & 3;     // 4 x 16B per 64B row
            const __half* src;
            if      (sub == 0) src = Ah + (long long)(bm0 + row) * lda + kc + seg * 8;
            else if (sub == 1) src = Al + (long long)(bm0 + row) * lda + kc + seg * 8;
            else if (sub == 2) src = Bh + (long long)(bn0 + row) * ldb + kc + seg * 8;
            else               src = Bl + (long long)(bn0 + row) * ldb + kc + seg * 8;
            cpa16(base + sub * SUBT + row * PITCH + seg * 16, src);
        }
    };

    float acc[2][8][4];
    #pragma unroll
    for (int i = 0; i < 2; i++)
        #pragma unroll
        for (int j = 0; j < 8; j++)
            #pragma unroll
            for (int e = 0; e < 4; e++) acc[i][j][e] = 0.0f;

    stage(0); cpa_commit();
    stage(1); cpa_commit();

    // ldmatrix lane address components (constant across chunks)
    const int arow = wm * 32 + (lane & 15);          // + mt*16
    const int asel = (lane >> 4);                    // 16B chunk within kstep
    const int brow = wn * 64 + (lane & 7) + ((lane >> 4) << 3);  // + pr*16
    const int bsel = (lane >> 3) & 1;

    for (int i = 0; i < nk; i++) {
        if (i + 1 < nk) cpa_wait1(); else cpa_wait0();
        __syncthreads();
        const unsigned base = sb + (i & 1) * STAGE;

        #pragma unroll
        for (int ks = 0; ks < 2; ks++) {
            unsigned ah[2][4], al[2][4];
            #pragma unroll
            for (int mt = 0; mt < 2; mt++) {
                const unsigned off = (arow + mt * 16) * PITCH + (ks * 2 + asel) * 16;
                ldsm4(ah[mt], base + off);
                if (NPASS == 3) ldsm4(al[mt], base + SUBT + off);
            }
            #pragma unroll
            for (int pr = 0; pr < 4; pr++) {
                unsigned bh[4], bl[4];
                const unsigned off = (brow + pr * 16) * PITCH + (ks * 2 + bsel) * 16;
                ldsm4(bh, base + 2 * SUBT + off);
                ldsm4(bl, base + 3 * SUBT + off);
                #pragma unroll
                for (int mt = 0; mt < 2; mt++)
                    #pragma unroll
                    for (int hf = 0; hf < 2; hf++) {
                        float* c = acc[mt][pr * 2 + hf];
                        mma16816(c, ah[mt], &bh[hf * 2]);
                        mma16816(c, ah[mt], &bl[hf * 2]);
                        if (NPASS == 3) mma16816(c, al[mt], &bh[hf * 2]);
                    }
            }
        }
        __syncthreads();
        if (i + 2 < nk) { stage(i + 2); cpa_commit(); }
    }

    // Epilogue
    const int er = bm0 + wm * 32 + (lane >> 2);
    const int ec = bn0 + wn * 64 + (lane & 3) * 2;
    #pragma unroll
    for (int mt = 0; mt < 2; mt++)
        #pragma unroll
        for (int nt = 0; nt < 8; nt++) {
            const float* c = acc[mt][nt];
            const int row = er + mt * 16;
            const int col = ec + nt * 8;
            const long long gi0 = coff + (long long)row * ldc + col;
            const long long gi1 = coff + (long long)(row + 8) * ldc + col;
            if (EPI == 0) {
                *(float2*)(Cf + gi0) = make_float2(c[0] * scale, c[1] * scale);
                *(float2*)(Cf + gi1) = make_float2(c[2] * scale, c[3] * scale);
            } else if (EPI == 1) {
                *(__half2*)(Chi + gi0) = __halves2half2(
                    __float2half(c[0] * scale), __float2half(c[1] * scale));
                *(__half2*)(Chi + gi1) = __halves2half2(
                    __float2half(c[2] * scale), __float2half(c[3] * scale));
            } else {
                // RoPE on the adjacent (even, odd) column pair, then fp16 split
                const int ip  = (col & 127) >> 1;
                const int s0r = row & (S_ - 1);
                const int s1r = (row + 8) & (S_ - 1);
                const float c0 = cs[s0r * 64 + ip], sv0 = sn[s0r * 64 + ip];
                const float c1 = cs[s1r * 64 + ip], sv1 = sn[s1r * 64 + ip];
                const float o0 = c[0] * c0 - c[1] * sv0;
                const float o1 = c[0] * sv0 + c[1] * c0;
                const float o2 = c[2] * c1 - c[3] * sv1;
                const float o3 = c[2] * sv1 + c[3] * c1;
                const __half h0 = __float2half(o0), h1 = __float2half(o1);
                const __half h2 = __float2half(o2), h3 = __float2half(o3);
                *(__half2*)(Chi + gi0) = __halves2half2(h0, h1);
                *(__half2*)(Chi + gi1) = __halves2half2(h2, h3);
                if (EPI == 3) {
                    *(__half2*)(Clo + gi0) = __halves2half2(
                        __float2half(o0 - __half2float(h0)),
                        __float2half(o1 - __half2float(h1)));
                    *(__half2*)(Clo + gi1) = __halves2half2(
                        __float2half(o2 - __half2float(h2)),
                        __float2half(o3 - __half2float(h3)));
                }
            }
        }
}

// ---------------------------------------------------------------------------
// Elementwise fp32 -> fp16 split.  LO=1: write (hi, lo);  LO=0: hi only.
// ---------------------------------------------------------------------------
template <int LO>
__global__ __launch_bounds__(256)
void split_k(const float4* __restrict__ s, __half2* __restrict__ h2,
             __half2* __restrict__ l2, int n4)
{
    int i = blockIdx.x * 256 + threadIdx.x;
    if (i >= n4) return;
    float4 v = s[i];
    __half hx = __float2half(v.x), hy = __float2half(v.y);
    __half hz = __float2half(v.z), hw = __float2half(v.w);
    h2[2 * i]     = __halves2half2(hx, hy);
    h2[2 * i + 1] = __halves2half2(hz, hw);
    if (LO) {
        l2[2 * i]     = __halves2half2(__float2half(v.x - __half2float(hx)),
                                       __float2half(v.y - __half2float(hy)));
        l2[2 * i + 1] = __halves2half2(__float2half(v.z - __half2float(hz)),
                                       __float2half(v.w - __half2float(hw)));
    }
}

// ---------------------------------------------------------------------------
// V transpose + split: vf32 [b,s,kv,d] -> vt hi/lo [b,kv,d,s]
// ---------------------------------------------------------------------------
__global__ __launch_bounds__(256)
void tsplit_v_k(const float* __restrict__ v,
                __half* __restrict__ hi, __half* __restrict__ lo)
{
    __shared__ float tile[32][33];
    const int bz = blockIdx.z;
    const int b = bz >> 3, kv = bz & 7;
    const int s0 = blockIdx.x * 32, d0 = blockIdx.y * 32;
    const int tx = threadIdx.x & 31, ty = threadIdx.x >> 5;

    #pragma unroll
    for (int j = 0; j < 4; j++) {
        int s = s0 + ty + j * 8;
        tile[ty + j * 8][tx] = v[((size_t)(b * S_ + s) * NKV_ + kv) * HD_ + d0 + tx];
    }
    __syncthreads();
    #pragma unroll
    for (int j = 0; j < 4; j++) {
        int d = d0 + ty + j * 8;
        float val = tile[tx][ty + j * 8];
        size_t o = ((size_t)(b * NKV_ + kv) * HD_ + d) * S_ + s0 + tx;
        __half h = __float2half(val);
        hi[o] = h;
        lo[o] = __float2half(val - __half2float(h));
    }
}

// ---------------------------------------------------------------------------
// Causal softmax, register-resident: ONE global read of the row, exp once,
// fp16 hi-only out. Zero-fills only to the next 128-col boundary (= PV kcap).
// ---------------------------------------------------------------------------
__global__ __launch_bounds__(256)
void softmax_k(const float* __restrict__ sc, __half* __restrict__ phi)
{
    const long long row = blockIdx.x;
    const int q = (int)(row % S_);
    const float* p = sc + row * (long long)S_;
    __half* oh = phi + row * (long long)S_;
    const int L = q + 1;
    const int tid = threadIdx.x;
    __shared__ float red[8];

    float r[8];
    float m = -1e30f;
    #pragma unroll
    for (int j = 0; j < 8; j++) {
        const int i = tid + j * 256;
        r[j] = (i < L) ? p[i] : -1e30f;
        m = fmaxf(m, r[j]);
    }
    #pragma unroll
    for (int o = 16; o; o >>= 1) m = fmaxf(m, __shfl_xor_sync(0xffffffffu, m, o));
    if ((tid & 31) == 0) red[tid >> 5] = m;
    __syncthreads();
    m = red[0];
    #pragma unroll
    for (int i = 1; i < 8; i++) m = fmaxf(m, red[i]);
    __syncthreads();

    float s = 0.0f;
    #pragma unroll
    for (int j = 0; j < 8; j++) {
        const int i = tid + j * 256;
        r[j] = (i < L) ? expf(r[j] - m) : 0.0f;
        s += r[j];
    }
    #pragma unroll
    for (int o = 16; o; o >>= 1) s += __shfl_xor_sync(0xffffffffu, s, o);
    if ((tid & 31) == 0) red[tid >> 5] = s;
    __syncthreads();
    s = red[0];
    #pragma unroll
    for (int i = 1; i < 8; i++) s += red[i];

    const float inv = 1.0f / s;
    #pragma unroll
    for (int j = 0; j < 8; j++) {
        const int i = tid + j * 256;
        if (i < L) oh[i] = __float2half(r[j] * inv);
    }
    const int zend = ((q >> 7) + 1) << 7;   // next 128 boundary (= PV kcap limit)
    const __half z = __float2half(0.0f);
    for (int i = L + tid; i < zend; i += 256) oh[i] = z;
}

// ---------------------------------------------------------------------------
// Inputs (metadata order): x, wq, wk, wv, wo, freqs_cos, freqs_sin
// ---------------------------------------------------------------------------
extern "C" void kernel_launch(void* const* d_in, const int* in_sizes, int n_in,
                              void* d_out, int out_size)
{
    const float* x  = (const float*)d_in[0];
    const float* wq = (const float*)d_in[1];
    const float* wk = (const float*)d_in[2];
    const float* wv = (const float*)d_in[3];
    const float* wo = (const float*)d_in[4];
    const float* fc = (const float*)d_in[5];
    const float* fs = (const float*)d_in[6];
    float* out = (float*)d_out;

    __half *xhi, *wqhi, *wqlo, *wkhi, *wklo, *wvhi, *wvlo, *wohi, *wolo;
    __half *qhi, *khi, *klo, *vthi, *vtlo, *phi, *ahi;
    float *vf, *sp;
    cudaGetSymbolAddress((void**)&xhi,  g_xhi);
    cudaGetSymbolAddress((void**)&wqhi, g_wqhi); cudaGetSymbolAddress((void**)&wqlo, g_wqlo);
    cudaGetSymbolAddress((void**)&wkhi, g_wkhi); cudaGetSymbolAddress((void**)&wklo, g_wklo);
    cudaGetSymbolAddress((void**)&wvhi, g_wvhi); cudaGetSymbolAddress((void**)&wvlo, g_wvlo);
    cudaGetSymbolAddress((void**)&wohi, g_wohi); cudaGetSymbolAddress((void**)&wolo, g_wolo);
    cudaGetSymbolAddress((void**)&vf, g_vf);
    cudaGetSymbolAddress((void**)&qhi, g_qhi);
    cudaGetSymbolAddress((void**)&khi, g_khi);   cudaGetSymbolAddress((void**)&klo, g_klo);
    cudaGetSymbolAddress((void**)&vthi, g_vthi); cudaGetSymbolAddress((void**)&vtlo, g_vtlo);
    cudaGetSymbolAddress((void**)&sp, g_sc);
    cudaGetSymbolAddress((void**)&phi, g_phi);
    cudaGetSymbolAddress((void**)&ahi, g_ahi);

    cudaFuncSetAttribute(gemm_mma<0,2>, cudaFuncAttributeMaxDynamicSharedMemorySize, SMEM_SZ);
    cudaFuncSetAttribute(gemm_mma<1,2>, cudaFuncAttributeMaxDynamicSharedMemorySize, SMEM_SZ);
    cudaFuncSetAttribute(gemm_mma<2,2>, cudaFuncAttributeMaxDynamicSharedMemorySize, SMEM_SZ);
    cudaFuncSetAttribute(gemm_mma<3,2>, cudaFuncAttributeMaxDynamicSharedMemorySize, SMEM_SZ);

    const float scale = 0.08838834764831845f;  // 1/sqrt(128)

    // 1) split inputs into fp16 hi/lo (x: hi only — lo is never read)
    split_k<0><<<16384, 256>>>((const float4*)x,  (__half2*)xhi,  nullptr,        4194304);
    split_k<1><<<16384, 256>>>((const float4*)wq, (__half2*)wqhi, (__half2*)wqlo, 4194304);
    split_k<1><<<4096,  256>>>((const float4*)wk, (__half2*)wkhi, (__half2*)wklo, 1048576);
    split_k<1><<<4096,  256>>>((const float4*)wv, (__half2*)wvhi, (__half2*)wvlo, 1048576);
    split_k<1><<<16384, 256>>>((const float4*)wo, (__half2*)wohi, (__half2*)wolo, 4194304);

    // 2) projections (2-pass fp16); Q and K fuse RoPE+split in the epilogue
    gemm_mma<2,2><<<dim3(32, 32, 1), 256, SMEM_SZ>>>(          // q -> qhi (rope)
        xhi, nullptr, wqhi, wqlo, nullptr, qhi, nullptr, fc, fs,
        DIM_, DIM_, DIM_, DIM_, 1, 1, 0, 0, 0, 0, 0, 0, 1.0f, 0, 0);
    gemm_mma<3,2><<<dim3(8, 32, 1), 256, SMEM_SZ>>>(           // k -> khi,klo (rope)
        xhi, nullptr, wkhi, wklo, nullptr, khi, klo, fc, fs,
        DIM_, DIM_, DIM_, NKV_ * HD_, 1, 1, 0, 0, 0, 0, 0, 0, 1.0f, 0, 0);
    gemm_mma<0,2><<<dim3(8, 32, 1), 256, SMEM_SZ>>>(           // v -> vf (fp32)
        xhi, nullptr, wvhi, wvlo, vf, nullptr, nullptr, nullptr, nullptr,
        DIM_, DIM_, DIM_, NKV_ * HD_, 1, 1, 0, 0, 0, 0, 0, 0, 1.0f, 0, 0);

    // 3) V transpose + split
    tsplit_v_k<<<dim3(S_ / 32, HD_ / 32, B_ * NKV_), 256>>>(vf, vthi, vtlo);

    // 4) scores = scale * Q K^T  (causal tile skip, 2-pass: qhi*(khi+klo))
    gemm_mma<0,2><<<dim3(16, 16, B_ * NH_), 256, SMEM_SZ>>>(
        qhi, nullptr, khi, klo, sp, nullptr, nullptr, nullptr, nullptr,
        HD_, NH_ * HD_, NKV_ * HD_, S_,
        NH_, 4,
        (long long)HD_, (long long)S_ * NH_ * HD_,
        (long long)HD_, (long long)S_ * NKV_ * HD_,
        (long long)S_ * S_, (long long)NH_ * S_ * S_,
        scale, 1, 0);

    // 5) softmax -> probs hi only (single-read, register-resident)
    softmax_k<<<B_ * NH_ * S_, 256>>>(sp, phi);

    // 6) attn = P V  (K capped causally; 2-pass: phi*(vthi+vtlo); hi-only out)
    gemm_mma<1,2><<<dim3(1, 16, B_ * NH_), 256, SMEM_SZ>>>(
        phi, nullptr, vthi, vtlo, nullptr, ahi, nullptr, nullptr, nullptr,
        S_, S_, S_, NH_ * HD_,
        NH_, 4,
        (long long)S_ * S_, (long long)NH_ * S_ * S_,
        (long long)HD_ * S_, (long long)NKV_ * HD_ * S_,
        (long long)HD_, (long long)S_ * NH_ * HD_,
        1.0f, 0, 1);

    // 7) output projection (2-pass fp16, reads ahi only)
    gemm_mma<0,2><<<dim3(32, 32, 1), 256, SMEM_SZ>>>(
        ahi, nullptr, wohi, wolo, out, nullptr, nullptr, nullptr, nullptr,
        DIM_, DIM_, DIM_, DIM_, 1, 1, 0, 0, 0, 0, 0, 0, 1.0f, 0, 0);
}

// round 11
// speedup vs baseline: 1.9890x; 1.0689x over previous
#include <cuda_runtime.h>
#include <cuda_fp16.h>
#include <math.h>

// Problem constants
constexpr int B_   = 2;
constexpr int S_   = 2048;
constexpr int DIM_ = 4096;
constexpr int NH_  = 32;
constexpr int NKV_ = 8;
constexpr int HD_  = 128;

// ---------------------------------------------------------------------------
// Scratch (module-scope device arrays; allocation-free at launch time)
// klo / vtlo are gone: QK and PV are now 1-pass (hi*hi).
// ---------------------------------------------------------------------------
__device__ __half g_xhi[16777216];                       // x hi
__device__ __half g_wqhi[16777216], g_wqlo[16777216];
__device__ __half g_wkhi[4194304],  g_wklo[4194304];
__device__ __half g_wvhi[4194304],  g_wvlo[4194304];
__device__ __half g_wohi[16777216], g_wolo[16777216];
__device__ float  g_vf[4194304];                         // v fp32 (pre-transpose)
__device__ __half g_qhi[16777216];                       // q hi post-rope
__device__ __half g_khi[4194304];                        // k hi post-rope
__device__ __half g_vthi[4194304];                       // V transposed [b,kv,d,s]
__device__ float  g_sc[268435456];                       // scores fp32 [b,h,q,k]
__device__ __half g_phi[268435456];                      // probs hi
__device__ __half g_ahi[16777216];                       // attn hi

// ---------------------------------------------------------------------------
// PTX helpers — sm_80-era only (compute_103 virtual arch: NO tcgen05)
// ---------------------------------------------------------------------------
__device__ __forceinline__ unsigned smem_u32(const void* p) {
    return (unsigned)__cvta_generic_to_shared(p);
}
__device__ __forceinline__ void cpa16(unsigned dst, const void* src) {
    asm volatile("cp.async.cg.shared.global [%0], [%1], 16;" :: "r"(dst), "l"(src) : "memory");
}
__device__ __forceinline__ void cpa_commit() {
    asm volatile("cp.async.commit_group;" ::: "memory");
}
__device__ __forceinline__ void cpa_wait1() {
    asm volatile("cp.async.wait_group 1;" ::: "memory");
}
__device__ __forceinline__ void cpa_wait0() {
    asm volatile("cp.async.wait_group 0;" ::: "memory");
}
__device__ __forceinline__ void ldsm4(unsigned* r, unsigned a) {
    asm volatile("ldmatrix.sync.aligned.m8n8.x4.shared.b16 {%0,%1,%2,%3}, [%4];"
                 : "=r"(r[0]), "=r"(r[1]), "=r"(r[2]), "=r"(r[3]) : "r"(a));
}
__device__ __forceinline__ void mma16816(float* c, const unsigned* a, const unsigned* b) {
    asm volatile("mma.sync.aligned.m16n8k16.row.col.f32.f16.f16.f32 "
                 "{%0,%1,%2,%3}, {%4,%5,%6,%7}, {%8,%9}, {%0,%1,%2,%3};"
                 : "+f"(c[0]), "+f"(c[1]), "+f"(c[2]), "+f"(c[3])
                 : "r"(a[0]), "r"(a[1]), "r"(a[2]), "r"(a[3]), "r"(b[0]), "r"(b[1]));
}

// SMEM geometry: rows of 32 halves (64B) padded to 80B pitch -> conflict-free
// ldmatrix (8-row phase banks: r*20 mod 32 all distinct) and 16B-aligned cp.async.
constexpr int PITCH   = 80;
constexpr int SUBT    = 128 * PITCH;   // 10240 B per operand subtile
constexpr int STAGE   = 4 * SUBT;      // Ahi|Alo|Bhi|Blo = 40960 B
constexpr int SMEM_SZ = 2 * STAGE;     // double buffered = 81920 B

// ---------------------------------------------------------------------------
// fp16 split GEMM via mma.sync: C[m,n] = scale * sum_k A[m,k]*B[n,k]
//   NPASS=3: ah*bh + ah*bl + al*bh   (error ~2^-22)
//   NPASS=2: ah*bh + ah*bl           (A rounded; error ~2^-11 w/ cancellation)
//   NPASS=1: ah*bh                   (both rounded; error ~2^-10.5)
//   EPI=0: fp32 C.          EPI=1: fp16 hi-only C.
//   EPI=2: RoPE -> fp16 hi. EPI=3: RoPE -> fp16 hi/lo.
//   causal=1: skip tiles above diagonal.  kcap=1: K capped at bm0+128.
// ---------------------------------------------------------------------------
template <int EPI, int NPASS>
__global__ __launch_bounds__(256, 2)
void gemm_mma(const __half* __restrict__ Ahi, const __half* __restrict__ Alo,
              const __half* __restrict__ Bhi, const __half* __restrict__ Blo,
              float* __restrict__ Cf, __half* __restrict__ Chi, __half* __restrict__ Clo,
              const float* __restrict__ cs, const float* __restrict__ sn,
              int K, int lda, int ldb, int ldc,
              int zdiv, int bdiv,
              long long sA1, long long sA2, long long sB1, long long sB2,
              long long sC1, long long sC2,
              float scale, int causal, int kcap)
{
    const int bm0 = blockIdx.y * 128;
    const int bn0 = blockIdx.x * 128;
    if (causal && bn0 > bm0) return;

    const int z  = blockIdx.z;
    const int z2 = z / zdiv;
    const int z1 = z - z2 * zdiv;
    const __half* Ah = Ahi + z2 * sA2 + (long long)z1 * sA1;
    const __half* Al = (NPASS == 3) ? Alo + z2 * sA2 + (long long)z1 * sA1 : nullptr;
    const __half* Bh = Bhi + z2 * sB2 + (long long)(z1 / bdiv) * sB1;
    const __half* Bl = (NPASS >= 2) ? Blo + z2 * sB2 + (long long)(z1 / bdiv) * sB1 : nullptr;
    const long long coff = z2 * sC2 + (long long)z1 * sC1;

    extern __shared__ char smem[];
    const unsigned sb = smem_u32(smem);
    const int tid  = threadIdx.x;
    const int lane = tid & 31;
    const int wid  = tid >> 5;
    const int wm   = wid & 3;     // 4 warp-rows x 32
    const int wn   = wid >> 2;    // 2 warp-cols x 64

    int Keff = K;
    if (kcap) { int c = bm0 + 128; if (c < Keff) Keff = c; }
    const int nk = Keff >> 5;     // KC = 32

    auto stage = [&](int si) {
        const unsigned base = sb + (si & 1) * STAGE;
        const int kc = si * 32;
        #pragma unroll
        for (int it = 0; it < 8; it++) {
            const int sub = it >> 1;                 // 0:Ahi 1:Alo 2:Bhi 3:Blo
            if (NPASS < 3 && sub == 1) continue;     // Alo unused below 3-pass
            if (NPASS < 2 && sub == 3) continue;     // Blo unused below 2-pass
            const int w   = (tid + it * 256) & 511;
            const int row = w >> 2, seg = w & 3;     // 4 x 16B per 64B row
            const __half* src;
            if      (sub == 0) src = Ah + (long long)(bm0 + row) * lda + kc + seg * 8;
            else if (sub == 1) src = Al + (long long)(bm0 + row) * lda + kc + seg * 8;
            else if (sub == 2) src = Bh + (long long)(bn0 + row) * ldb + kc + seg * 8;
            else               src = Bl + (long long)(bn0 + row) * ldb + kc + seg * 8;
            cpa16(base + sub * SUBT + row * PITCH + seg * 16, src);
        }
    };

    float acc[2][8][4];
    #pragma unroll
    for (int i = 0; i < 2; i++)
        #pragma unroll
        for (int j = 0; j < 8; j++)
            #pragma unroll
            for (int e = 0; e < 4; e++) acc[i][j][e] = 0.0f;

    stage(0); cpa_commit();
    stage(1); cpa_commit();

    // ldmatrix lane address components (constant across chunks)
    const int arow = wm * 32 + (lane & 15);          // + mt*16
    const int asel = (lane >> 4);                    // 16B chunk within kstep
    const int brow = wn * 64 + (lane & 7) + ((lane >> 4) << 3);  // + pr*16
    const int bsel = (lane >> 3) & 1;

    for (int i = 0; i < nk; i++) {
        if (i + 1 < nk) cpa_wait1(); else cpa_wait0();
        __syncthreads();
        const unsigned base = sb + (i & 1) * STAGE;

        #pragma unroll
        for (int ks = 0; ks < 2; ks++) {
            unsigned ah[2][4], al[2][4];
            #pragma unroll
            for (int mt = 0; mt < 2; mt++) {
                const unsigned off = (arow + mt * 16) * PITCH + (ks * 2 + asel) * 16;
                ldsm4(ah[mt], base + off);
                if (NPASS == 3) ldsm4(al[mt], base + SUBT + off);
            }
            #pragma unroll
            for (int pr = 0; pr < 4; pr++) {
                unsigned bh[4], bl[4];
                const unsigned off = (brow + pr * 16) * PITCH + (ks * 2 + bsel) * 16;
                ldsm4(bh, base + 2 * SUBT + off);
                if (NPASS >= 2) ldsm4(bl, base + 3 * SUBT + off);
                #pragma unroll
                for (int mt = 0; mt < 2; mt++)
                    #pragma unroll
                    for (int hf = 0; hf < 2; hf++) {
                        float* c = acc[mt][pr * 2 + hf];
                        mma16816(c, ah[mt], &bh[hf * 2]);
                        if (NPASS >= 2) mma16816(c, ah[mt], &bl[hf * 2]);
                        if (NPASS == 3) mma16816(c, al[mt], &bh[hf * 2]);
                    }
            }
        }
        __syncthreads();
        if (i + 2 < nk) { stage(i + 2); cpa_commit(); }
    }

    // Epilogue
    const int er = bm0 + wm * 32 + (lane >> 2);
    const int ec = bn0 + wn * 64 + (lane & 3) * 2;
    #pragma unroll
    for (int mt = 0; mt < 2; mt++)
        #pragma unroll
        for (int nt = 0; nt < 8; nt++) {
            const float* c = acc[mt][nt];
            const int row = er + mt * 16;
            const int col = ec + nt * 8;
            const long long gi0 = coff + (long long)row * ldc + col;
            const long long gi1 = coff + (long long)(row + 8) * ldc + col;
            if (EPI == 0) {
                *(float2*)(Cf + gi0) = make_float2(c[0] * scale, c[1] * scale);
                *(float2*)(Cf + gi1) = make_float2(c[2] * scale, c[3] * scale);
            } else if (EPI == 1) {
                *(__half2*)(Chi + gi0) = __halves2half2(
                    __float2half(c[0] * scale), __float2half(c[1] * scale));
                *(__half2*)(Chi + gi1) = __halves2half2(
                    __float2half(c[2] * scale), __float2half(c[3] * scale));
            } else {
                // RoPE on the adjacent (even, odd) column pair, then fp16 split
                const int ip  = (col & 127) >> 1;
                const int s0r = row & (S_ - 1);
                const int s1r = (row + 8) & (S_ - 1);
                const float c0 = cs[s0r * 64 + ip], sv0 = sn[s0r * 64 + ip];
                const float c1 = cs[s1r * 64 + ip], sv1 = sn[s1r * 64 + ip];
                const float o0 = c[0] * c0 - c[1] * sv0;
                const float o1 = c[0] * sv0 + c[1] * c0;
                const float o2 = c[2] * c1 - c[3] * sv1;
                const float o3 = c[2] * sv1 + c[3] * c1;
                const __half h0 = __float2half(o0), h1 = __float2half(o1);
                const __half h2 = __float2half(o2), h3 = __float2half(o3);
                *(__half2*)(Chi + gi0) = __halves2half2(h0, h1);
                *(__half2*)(Chi + gi1) = __halves2half2(h2, h3);
                if (EPI == 3) {
                    *(__half2*)(Clo + gi0) = __halves2half2(
                        __float2half(o0 - __half2float(h0)),
                        __float2half(o1 - __half2float(h1)));
                    *(__half2*)(Clo + gi1) = __halves2half2(
                        __float2half(o2 - __half2float(h2)),
                        __float2half(o3 - __half2float(h3)));
                }
            }
        }
}

// ---------------------------------------------------------------------------
// Elementwise fp32 -> fp16 split.  LO=1: write (hi, lo);  LO=0: hi only.
// ---------------------------------------------------------------------------
template <int LO>
__global__ __launch_bounds__(256)
void split_k(const float4* __restrict__ s, __half2* __restrict__ h2,
             __half2* __restrict__ l2, int n4)
{
    int i = blockIdx.x * 256 + threadIdx.x;
    if (i >= n4) return;
    float4 v = s[i];
    __half hx = __float2half(v.x), hy = __float2half(v.y);
    __half hz = __float2half(v.z), hw = __float2half(v.w);
    h2[2 * i]     = __halves2half2(hx, hy);
    h2[2 * i + 1] = __halves2half2(hz, hw);
    if (LO) {
        l2[2 * i]     = __halves2half2(__float2half(v.x - __half2float(hx)),
                                       __float2half(v.y - __half2float(hy)));
        l2[2 * i + 1] = __halves2half2(__float2half(v.z - __half2float(hz)),
                                       __float2half(v.w - __half2float(hw)));
    }
}

// ---------------------------------------------------------------------------
// V transpose: vf32 [b,s,kv,d] -> vt hi fp16 [b,kv,d,s]  (lo is dead: PV 1-pass)
// ---------------------------------------------------------------------------
__global__ __launch_bounds__(256)
void tsplit_v_k(const float* __restrict__ v, __half* __restrict__ hi)
{
    __shared__ float tile[32][33];
    const int bz = blockIdx.z;
    const int b = bz >> 3, kv = bz & 7;
    const int s0 = blockIdx.x * 32, d0 = blockIdx.y * 32;
    const int tx = threadIdx.x & 31, ty = threadIdx.x >> 5;

    #pragma unroll
    for (int j = 0; j < 4; j++) {
        int s = s0 + ty + j * 8;
        tile[ty + j * 8][tx] = v[((size_t)(b * S_ + s) * NKV_ + kv) * HD_ + d0 + tx];
    }
    __syncthreads();
    #pragma unroll
    for (int j = 0; j < 4; j++) {
        int d = d0 + ty + j * 8;
        float val = tile[tx][ty + j * 8];
        size_t o = ((size_t)(b * NKV_ + kv) * HD_ + d) * S_ + s0 + tx;
        hi[o] = __float2half(val);
    }
}

// ---------------------------------------------------------------------------
// Causal softmax, register-resident: ONE global read of the row, exp once,
// fp16 hi-only out. Zero-fills only to the next 128-col boundary (= PV kcap).
// ---------------------------------------------------------------------------
__global__ __launch_bounds__(256)
void softmax_k(const float* __restrict__ sc, __half* __restrict__ phi)
{
    const long long row = blockIdx.x;
    const int q = (int)(row % S_);
    const float* p = sc + row * (long long)S_;
    __half* oh = phi + row * (long long)S_;
    const int L = q + 1;
    const int tid = threadIdx.x;
    __shared__ float red[8];

    float r[8];
    float m = -1e30f;
    #pragma unroll
    for (int j = 0; j < 8; j++) {
        const int i = tid + j * 256;
        r[j] = (i < L) ? p[i] : -1e30f;
        m = fmaxf(m, r[j]);
    }
    #pragma unroll
    for (int o = 16; o; o >>= 1) m = fmaxf(m, __shfl_xor_sync(0xffffffffu, m, o));
    if ((tid & 31) == 0) red[tid >> 5] = m;
    __syncthreads();
    m = red[0];
    #pragma unroll
    for (int i = 1; i < 8; i++) m = fmaxf(m, red[i]);
    __syncthreads();

    float s = 0.0f;
    #pragma unroll
    for (int j = 0; j < 8; j++) {
        const int i = tid + j * 256;
        r[j] = (i < L) ? expf(r[j] - m) : 0.0f;
        s += r[j];
    }
    #pragma unroll
    for (int o = 16; o; o >>= 1) s += __shfl_xor_sync(0xffffffffu, s, o);
    if ((tid & 31) == 0) red[tid >> 5] = s;
    __syncthreads();
    s = red[0];
    #pragma unroll
    for (int i = 1; i < 8; i++) s += red[i];

    const float inv = 1.0f / s;
    #pragma unroll
    for (int j = 0; j < 8; j++) {
        const int i = tid + j * 256;
        if (i < L) oh[i] = __float2half(r[j] * inv);
    }
    const int zend = ((q >> 7) + 1) << 7;   // next 128 boundary (= PV kcap limit)
    const __half z = __float2half(0.0f);
    for (int i = L + tid; i < zend; i += 256) oh[i] = z;
}

// ---------------------------------------------------------------------------
// Inputs (metadata order): x, wq, wk, wv, wo, freqs_cos, freqs_sin
// ---------------------------------------------------------------------------
extern "C" void kernel_launch(void* const* d_in, const int* in_sizes, int n_in,
                              void* d_out, int out_size)
{
    const float* x  = (const float*)d_in[0];
    const float* wq = (const float*)d_in[1];
    const float* wk = (const float*)d_in[2];
    const float* wv = (const float*)d_in[3];
    const float* wo = (const float*)d_in[4];
    const float* fc = (const float*)d_in[5];
    const float* fs = (const float*)d_in[6];
    float* out = (float*)d_out;

    __half *xhi, *wqhi, *wqlo, *wkhi, *wklo, *wvhi, *wvlo, *wohi, *wolo;
    __half *qhi, *khi, *vthi, *phi, *ahi;
    float *vf, *sp;
    cudaGetSymbolAddress((void**)&xhi,  g_xhi);
    cudaGetSymbolAddress((void**)&wqhi, g_wqhi); cudaGetSymbolAddress((void**)&wqlo, g_wqlo);
    cudaGetSymbolAddress((void**)&wkhi, g_wkhi); cudaGetSymbolAddress((void**)&wklo, g_wklo);
    cudaGetSymbolAddress((void**)&wvhi, g_wvhi); cudaGetSymbolAddress((void**)&wvlo, g_wvlo);
    cudaGetSymbolAddress((void**)&wohi, g_wohi); cudaGetSymbolAddress((void**)&wolo, g_wolo);
    cudaGetSymbolAddress((void**)&vf, g_vf);
    cudaGetSymbolAddress((void**)&qhi, g_qhi);
    cudaGetSymbolAddress((void**)&khi, g_khi);
    cudaGetSymbolAddress((void**)&vthi, g_vthi);
    cudaGetSymbolAddress((void**)&sp, g_sc);
    cudaGetSymbolAddress((void**)&phi, g_phi);
    cudaGetSymbolAddress((void**)&ahi, g_ahi);

    cudaFuncSetAttribute(gemm_mma<0,1>, cudaFuncAttributeMaxDynamicSharedMemorySize, SMEM_SZ);
    cudaFuncSetAttribute(gemm_mma<1,1>, cudaFuncAttributeMaxDynamicSharedMemorySize, SMEM_SZ);
    cudaFuncSetAttribute(gemm_mma<0,2>, cudaFuncAttributeMaxDynamicSharedMemorySize, SMEM_SZ);
    cudaFuncSetAttribute(gemm_mma<2,2>, cudaFuncAttributeMaxDynamicSharedMemorySize, SMEM_SZ);

    const float scale = 0.08838834764831845f;  // 1/sqrt(128)

    // 1) split inputs into fp16 hi/lo (x: hi only)
    split_k<0><<<16384, 256>>>((const float4*)x,  (__half2*)xhi,  nullptr,        4194304);
    split_k<1><<<16384, 256>>>((const float4*)wq, (__half2*)wqhi, (__half2*)wqlo, 4194304);
    split_k<1><<<4096,  256>>>((const float4*)wk, (__half2*)wkhi, (__half2*)wklo, 1048576);
    split_k<1><<<4096,  256>>>((const float4*)wv, (__half2*)wvhi, (__half2*)wvlo, 1048576);
    split_k<1><<<16384, 256>>>((const float4*)wo, (__half2*)wohi, (__half2*)wolo, 4194304);

    // 2) projections (2-pass fp16); Q and K fuse RoPE+hi-split in the epilogue
    gemm_mma<2,2><<<dim3(32, 32, 1), 256, SMEM_SZ>>>(          // q -> qhi (rope)
        xhi, nullptr, wqhi, wqlo, nullptr, qhi, nullptr, fc, fs,
        DIM_, DIM_, DIM_, DIM_, 1, 1, 0, 0, 0, 0, 0, 0, 1.0f, 0, 0);
    gemm_mma<2,2><<<dim3(8, 32, 1), 256, SMEM_SZ>>>(           // k -> khi (rope)
        xhi, nullptr, wkhi, wklo, nullptr, khi, nullptr, fc, fs,
        DIM_, DIM_, DIM_, NKV_ * HD_, 1, 1, 0, 0, 0, 0, 0, 0, 1.0f, 0, 0);
    gemm_mma<0,2><<<dim3(8, 32, 1), 256, SMEM_SZ>>>(           // v -> vf (fp32)
        xhi, nullptr, wvhi, wvlo, vf, nullptr, nullptr, nullptr, nullptr,
        DIM_, DIM_, DIM_, NKV_ * HD_, 1, 1, 0, 0, 0, 0, 0, 0, 1.0f, 0, 0);

    // 3) V transpose (hi only)
    tsplit_v_k<<<dim3(S_ / 32, HD_ / 32, B_ * NKV_), 256>>>(vf, vthi);

    // 4) scores = scale * Q K^T  (causal tile skip, 1-pass: qhi*khi)
    gemm_mma<0,1><<<dim3(16, 16, B_ * NH_), 256, SMEM_SZ>>>(
        qhi, nullptr, khi, nullptr, sp, nullptr, nullptr, nullptr, nullptr,
        HD_, NH_ * HD_, NKV_ * HD_, S_,
        NH_, 4,
        (long long)HD_, (long long)S_ * NH_ * HD_,
        (long long)HD_, (long long)S_ * NKV_ * HD_,
        (long long)S_ * S_, (long long)NH_ * S_ * S_,
        scale, 1, 0);

    // 5) softmax -> probs hi only (single-read, register-resident)
    softmax_k<<<B_ * NH_ * S_, 256>>>(sp, phi);

    // 6) attn = P V  (K capped causally; 1-pass: phi*vthi; hi-only out)
    gemm_mma<1,1><<<dim3(1, 16, B_ * NH_), 256, SMEM_SZ>>>(
        phi, nullptr, vthi, nullptr, nullptr, ahi, nullptr, nullptr, nullptr,
        S_, S_, S_, NH_ * HD_,
        NH_, 4,
        (long long)S_ * S_, (long long)NH_ * S_ * S_,
        (long long)HD_ * S_, (long long)NKV_ * HD_ * S_,
        (long long)HD_, (long long)S_ * NH_ * HD_,
        1.0f, 0, 1);

    // 7) output projection (2-pass fp16, reads ahi only)
    gemm_mma<0,2><<<dim3(32, 32, 1), 256, SMEM_SZ>>>(
        ahi, nullptr, wohi, wolo, out, nullptr, nullptr, nullptr, nullptr,
        DIM_, DIM_, DIM_, DIM_, 1, 1, 0, 0, 0, 0, 0, 0, 1.0f, 0, 0);
}

// round 12
// speedup vs baseline: 2.9333x; 1.4748x over previous
#include <cuda_runtime.h>
#include <cuda_fp16.h>
#include <math.h>

// Problem constants
constexpr int B_   = 2;
constexpr int S_   = 2048;
constexpr int DIM_ = 4096;
constexpr int NH_  = 32;
constexpr int NKV_ = 8;
constexpr int HD_  = 128;

// ---------------------------------------------------------------------------
// Scratch (module-scope device arrays; allocation-free at launch time)
// All GEMMs are now 1-pass (hi*hi): no lo arrays anywhere.
// ---------------------------------------------------------------------------
__device__ __half g_xhi[16777216];                       // x hi
__device__ __half g_wqhi[16777216];
__device__ __half g_wkhi[4194304];
__device__ __half g_wvhi[4194304];
__device__ __half g_wohi[16777216];
__device__ float  g_vf[4194304];                         // v fp32 (pre-transpose)
__device__ __half g_qhi[16777216];                       // q hi post-rope
__device__ __half g_khi[4194304];                        // k hi post-rope
__device__ __half g_vthi[4194304];                       // V transposed [b,kv,d,s]
__device__ float  g_sc[268435456];                       // scores fp32 [b,h,q,k]
__device__ __half g_phi[268435456];                      // probs hi
__device__ __half g_ahi[16777216];                       // attn hi

// ---------------------------------------------------------------------------
// PTX helpers — sm_80-era only (compute_103 virtual arch: NO tcgen05)
// ---------------------------------------------------------------------------
__device__ __forceinline__ unsigned smem_u32(const void* p) {
    return (unsigned)__cvta_generic_to_shared(p);
}
__device__ __forceinline__ void cpa16(unsigned dst, const void* src) {
    asm volatile("cp.async.cg.shared.global [%0], [%1], 16;" :: "r"(dst), "l"(src) : "memory");
}
__device__ __forceinline__ void cpa_commit() {
    asm volatile("cp.async.commit_group;" ::: "memory");
}
__device__ __forceinline__ void cpa_wait1() {
    asm volatile("cp.async.wait_group 1;" ::: "memory");
}
__device__ __forceinline__ void cpa_wait0() {
    asm volatile("cp.async.wait_group 0;" ::: "memory");
}
__device__ __forceinline__ void ldsm4(unsigned* r, unsigned a) {
    asm volatile("ldmatrix.sync.aligned.m8n8.x4.shared.b16 {%0,%1,%2,%3}, [%4];"
                 : "=r"(r[0]), "=r"(r[1]), "=r"(r[2]), "=r"(r[3]) : "r"(a));
}
__device__ __forceinline__ void mma16816(float* c, const unsigned* a, const unsigned* b) {
    asm volatile("mma.sync.aligned.m16n8k16.row.col.f32.f16.f16.f32 "
                 "{%0,%1,%2,%3}, {%4,%5,%6,%7}, {%8,%9}, {%0,%1,%2,%3};"
                 : "+f"(c[0]), "+f"(c[1]), "+f"(c[2]), "+f"(c[3])
                 : "r"(a[0]), "r"(a[1]), "r"(a[2]), "r"(a[3]), "r"(b[0]), "r"(b[1]));
}

// SMEM geometry: rows of 32 halves (64B) padded to 80B pitch -> conflict-free
// ldmatrix (8-row phase banks: r*20 mod 32 all distinct) and 16B-aligned cp.async.
constexpr int PITCH   = 80;
constexpr int SUBT    = 128 * PITCH;   // 10240 B per operand subtile
constexpr int STAGE   = 4 * SUBT;      // Ahi|Alo|Bhi|Blo slots = 40960 B
constexpr int SMEM_SZ = 2 * STAGE;     // double buffered = 81920 B

// ---------------------------------------------------------------------------
// fp16 split GEMM via mma.sync: C[m,n] = scale * sum_k A[m,k]*B[n,k]
//   NPASS=3: ah*bh + ah*bl + al*bh.  NPASS=2: ah*bh + ah*bl.  NPASS=1: ah*bh.
//   EPI=0: fp32 C.          EPI=1: fp16 hi-only C.
//   EPI=2: RoPE -> fp16 hi. EPI=3: RoPE -> fp16 hi/lo.
//   causal=1: skip tiles above diagonal.  kcap=1: K capped at bm0+128.
// ---------------------------------------------------------------------------
template <int EPI, int NPASS>
__global__ __launch_bounds__(256, 2)
void gemm_mma(const __half* __restrict__ Ahi, const __half* __restrict__ Alo,
              const __half* __restrict__ Bhi, const __half* __restrict__ Blo,
              float* __restrict__ Cf, __half* __restrict__ Chi, __half* __restrict__ Clo,
              const float* __restrict__ cs, const float* __restrict__ sn,
              int K, int lda, int ldb, int ldc,
              int zdiv, int bdiv,
              long long sA1, long long sA2, long long sB1, long long sB2,
              long long sC1, long long sC2,
              float scale, int causal, int kcap)
{
    const int bm0 = blockIdx.y * 128;
    const int bn0 = blockIdx.x * 128;
    if (causal && bn0 > bm0) return;

    const int z  = blockIdx.z;
    const int z2 = z / zdiv;
    const int z1 = z - z2 * zdiv;
    const __half* Ah = Ahi + z2 * sA2 + (long long)z1 * sA1;
    const __half* Al = (NPASS == 3) ? Alo + z2 * sA2 + (long long)z1 * sA1 : nullptr;
    const __half* Bh = Bhi + z2 * sB2 + (long long)(z1 / bdiv) * sB1;
    const __half* Bl = (NPASS >= 2) ? Blo + z2 * sB2 + (long long)(z1 / bdiv) * sB1 : nullptr;
    const long long coff = z2 * sC2 + (long long)z1 * sC1;

    extern __shared__ char smem[];
    const unsigned sb = smem_u32(smem);
    const int tid  = threadIdx.x;
    const int lane = tid & 31;
    const int wid  = tid >> 5;
    const int wm   = wid & 3;     // 4 warp-rows x 32
    const int wn   = wid >> 2;    // 2 warp-cols x 64

    int Keff = K;
    if (kcap) { int c = bm0 + 128; if (c < Keff) Keff = c; }
    const int nk = Keff >> 5;     // KC = 32

    auto stage = [&](int si) {
        const unsigned base = sb + (si & 1) * STAGE;
        const int kc = si * 32;
        #pragma unroll
        for (int it = 0; it < 8; it++) {
            const int sub = it >> 1;                 // 0:Ahi 1:Alo 2:Bhi 3:Blo
            if (NPASS < 3 && sub == 1) continue;     // Alo unused below 3-pass
            if (NPASS < 2 && sub == 3) continue;     // Blo unused below 2-pass
            const int w   = (tid + it * 256) & 511;
            const int row = w >> 2, seg = w & 3;     // 4 x 16B per 64B row
            const __half* src;
            if      (sub == 0) src = Ah + (long long)(bm0 + row) * lda + kc + seg * 8;
            else if (sub == 1) src = Al + (long long)(bm0 + row) * lda + kc + seg * 8;
            else if (sub == 2) src = Bh + (long long)(bn0 + row) * ldb + kc + seg * 8;
            else               src = Bl + (long long)(bn0 + row) * ldb + kc + seg * 8;
            cpa16(base + sub * SUBT + row * PITCH + seg * 16, src);
        }
    };

    float acc[2][8][4];
    #pragma unroll
    for (int i = 0; i < 2; i++)
        #pragma unroll
        for (int j = 0; j < 8; j++)
            #pragma unroll
            for (int e = 0; e < 4; e++) acc[i][j][e] = 0.0f;

    stage(0); cpa_commit();
    stage(1); cpa_commit();

    // ldmatrix lane address components (constant across chunks)
    const int arow = wm * 32 + (lane & 15);          // + mt*16
    const int asel = (lane >> 4);                    // 16B chunk within kstep
    const int brow = wn * 64 + (lane & 7) + ((lane >> 4) << 3);  // + pr*16
    const int bsel = (lane >> 3) & 1;

    for (int i = 0; i < nk; i++) {
        if (i + 1 < nk) cpa_wait1(); else cpa_wait0();
        __syncthreads();
        const unsigned base = sb + (i & 1) * STAGE;

        #pragma unroll
        for (int ks = 0; ks < 2; ks++) {
            unsigned ah[2][4], al[2][4];
            #pragma unroll
            for (int mt = 0; mt < 2; mt++) {
                const unsigned off = (arow + mt * 16) * PITCH + (ks * 2 + asel) * 16;
                ldsm4(ah[mt], base + off);
                if (NPASS == 3) ldsm4(al[mt], base + SUBT + off);
            }
            #pragma unroll
            for (int pr = 0; pr < 4; pr++) {
                unsigned bh[4], bl[4];
                const unsigned off = (brow + pr * 16) * PITCH + (ks * 2 + bsel) * 16;
                ldsm4(bh, base + 2 * SUBT + off);
                if (NPASS >= 2) ldsm4(bl, base + 3 * SUBT + off);
                #pragma unroll
                for (int mt = 0; mt < 2; mt++)
                    #pragma unroll
                    for (int hf = 0; hf < 2; hf++) {
                        float* c = acc[mt][pr * 2 + hf];
                        mma16816(c, ah[mt], &bh[hf * 2]);
                        if (NPASS >= 2) mma16816(c, ah[mt], &bl[hf * 2]);
                        if (NPASS == 3) mma16816(c, al[mt], &bh[hf * 2]);
                    }
            }
        }
        __syncthreads();
        if (i + 2 < nk) { stage(i + 2); cpa_commit(); }
    }

    // Epilogue
    const int er = bm0 + wm * 32 + (lane >> 2);
    const int ec = bn0 + wn * 64 + (lane & 3) * 2;
    #pragma unroll
    for (int mt = 0; mt < 2; mt++)
        #pragma unroll
        for (int nt = 0; nt < 8; nt++) {
            const float* c = acc[mt][nt];
            const int row = er + mt * 16;
            const int col = ec + nt * 8;
            const long long gi0 = coff + (long long)row * ldc + col;
            const long long gi1 = coff + (long long)(row + 8) * ldc + col;
            if (EPI == 0) {
                *(float2*)(Cf + gi0) = make_float2(c[0] * scale, c[1] * scale);
                *(float2*)(Cf + gi1) = make_float2(c[2] * scale, c[3] * scale);
            } else if (EPI == 1) {
                *(__half2*)(Chi + gi0) = __halves2half2(
                    __float2half(c[0] * scale), __float2half(c[1] * scale));
                *(__half2*)(Chi + gi1) = __halves2half2(
                    __float2half(c[2] * scale), __float2half(c[3] * scale));
            } else {
                // RoPE on the adjacent (even, odd) column pair, then fp16 split
                const int ip  = (col & 127) >> 1;
                const int s0r = row & (S_ - 1);
                const int s1r = (row + 8) & (S_ - 1);
                const float c0 = cs[s0r * 64 + ip], sv0 = sn[s0r * 64 + ip];
                const float c1 = cs[s1r * 64 + ip], sv1 = sn[s1r * 64 + ip];
                const float o0 = c[0] * c0 - c[1] * sv0;
                const float o1 = c[0] * sv0 + c[1] * c0;
                const float o2 = c[2] * c1 - c[3] * sv1;
                const float o3 = c[2] * sv1 + c[3] * c1;
                const __half h0 = __float2half(o0), h1 = __float2half(o1);
                const __half h2 = __float2half(o2), h3 = __float2half(o3);
                *(__half2*)(Chi + gi0) = __halves2half2(h0, h1);
                *(__half2*)(Chi + gi1) = __halves2half2(h2, h3);
                if (EPI == 3) {
                    *(__half2*)(Clo + gi0) = __halves2half2(
                        __float2half(o0 - __half2float(h0)),
                        __float2half(o1 - __half2float(h1)));
                    *(__half2*)(Clo + gi1) = __halves2half2(
                        __float2half(o2 - __half2float(h2)),
                        __float2half(o3 - __half2float(h3)));
                }
            }
        }
}

// ---------------------------------------------------------------------------
// Elementwise fp32 -> fp16 (hi only; lo path retained for template reuse)
// ---------------------------------------------------------------------------
template <int LO>
__global__ __launch_bounds__(256)
void split_k(const float4* __restrict__ s, __half2* __restrict__ h2,
             __half2* __restrict__ l2, int n4)
{
    int i = blockIdx.x * 256 + threadIdx.x;
    if (i >= n4) return;
    float4 v = s[i];
    __half hx = __float2half(v.x), hy = __float2half(v.y);
    __half hz = __float2half(v.z), hw = __float2half(v.w);
    h2[2 * i]     = __halves2half2(hx, hy);
    h2[2 * i + 1] = __halves2half2(hz, hw);
    if (LO) {
        l2[2 * i]     = __halves2half2(__float2half(v.x - __half2float(hx)),
                                       __float2half(v.y - __half2float(hy)));
        l2[2 * i + 1] = __halves2half2(__float2half(v.z - __half2float(hz)),
                                       __float2half(v.w - __half2float(hw)));
    }
}

// ---------------------------------------------------------------------------
// V transpose: vf32 [b,s,kv,d] -> vt hi fp16 [b,kv,d,s]
// ---------------------------------------------------------------------------
__global__ __launch_bounds__(256)
void tsplit_v_k(const float* __restrict__ v, __half* __restrict__ hi)
{
    __shared__ float tile[32][33];
    const int bz = blockIdx.z;
    const int b = bz >> 3, kv = bz & 7;
    const int s0 = blockIdx.x * 32, d0 = blockIdx.y * 32;
    const int tx = threadIdx.x & 31, ty = threadIdx.x >> 5;

    #pragma unroll
    for (int j = 0; j < 4; j++) {
        int s = s0 + ty + j * 8;
        tile[ty + j * 8][tx] = v[((size_t)(b * S_ + s) * NKV_ + kv) * HD_ + d0 + tx];
    }
    __syncthreads();
    #pragma unroll
    for (int j = 0; j < 4; j++) {
        int d = d0 + ty + j * 8;
        float val = tile[tx][ty + j * 8];
        size_t o = ((size_t)(b * NKV_ + kv) * HD_ + d) * S_ + s0 + tx;
        hi[o] = __float2half(val);
    }
}

// ---------------------------------------------------------------------------
// Causal softmax, register-resident: ONE global read of the row, exp once,
// fp16 hi-only out. Zero-fills only to the next 128-col boundary (= PV kcap).
// ---------------------------------------------------------------------------
__global__ __launch_bounds__(256)
void softmax_k(const float* __restrict__ sc, __half* __restrict__ phi)
{
    const long long row = blockIdx.x;
    const int q = (int)(row % S_);
    const float* p = sc + row * (long long)S_;
    __half* oh = phi + row * (long long)S_;
    const int L = q + 1;
    const int tid = threadIdx.x;
    __shared__ float red[8];

    float r[8];
    float m = -1e30f;
    #pragma unroll
    for (int j = 0; j < 8; j++) {
        const int i = tid + j * 256;
        r[j] = (i < L) ? p[i] : -1e30f;
        m = fmaxf(m, r[j]);
    }
    #pragma unroll
    for (int o = 16; o; o >>= 1) m = fmaxf(m, __shfl_xor_sync(0xffffffffu, m, o));
    if ((tid & 31) == 0) red[tid >> 5] = m;
    __syncthreads();
    m = red[0];
    #pragma unroll
    for (int i = 1; i < 8; i++) m = fmaxf(m, red[i]);
    __syncthreads();

    float s = 0.0f;
    #pragma unroll
    for (int j = 0; j < 8; j++) {
        const int i = tid + j * 256;
        r[j] = (i < L) ? expf(r[j] - m) : 0.0f;
        s += r[j];
    }
    #pragma unroll
    for (int o = 16; o; o >>= 1) s += __shfl_xor_sync(0xffffffffu, s, o);
    if ((tid & 31) == 0) red[tid >> 5] = s;
    __syncthreads();
    s = red[0];
    #pragma unroll
    for (int i = 1; i < 8; i++) s += red[i];

    const float inv = 1.0f / s;
    #pragma unroll
    for (int j = 0; j < 8; j++) {
        const int i = tid + j * 256;
        if (i < L) oh[i] = __float2half(r[j] * inv);
    }
    const int zend = ((q >> 7) + 1) << 7;   // next 128 boundary (= PV kcap limit)
    const __half z = __float2half(0.0f);
    for (int i = L + tid; i < zend; i += 256) oh[i] = z;
}

// ---------------------------------------------------------------------------
// Inputs (metadata order): x, wq, wk, wv, wo, freqs_cos, freqs_sin
// ---------------------------------------------------------------------------
extern "C" void kernel_launch(void* const* d_in, const int* in_sizes, int n_in,
                              void* d_out, int out_size)
{
    const float* x  = (const float*)d_in[0];
    const float* wq = (const float*)d_in[1];
    const float* wk = (const float*)d_in[2];
    const float* wv = (const float*)d_in[3];
    const float* wo = (const float*)d_in[4];
    const float* fc = (const float*)d_in[5];
    const float* fs = (const float*)d_in[6];
    float* out = (float*)d_out;

    __half *xhi, *wqhi, *wkhi, *wvhi, *wohi;
    __half *qhi, *khi, *vthi, *phi, *ahi;
    float *vf, *sp;
    cudaGetSymbolAddress((void**)&xhi,  g_xhi);
    cudaGetSymbolAddress((void**)&wqhi, g_wqhi);
    cudaGetSymbolAddress((void**)&wkhi, g_wkhi);
    cudaGetSymbolAddress((void**)&wvhi, g_wvhi);
    cudaGetSymbolAddress((void**)&wohi, g_wohi);
    cudaGetSymbolAddress((void**)&vf, g_vf);
    cudaGetSymbolAddress((void**)&qhi, g_qhi);
    cudaGetSymbolAddress((void**)&khi, g_khi);
    cudaGetSymbolAddress((void**)&vthi, g_vthi);
    cudaGetSymbolAddress((void**)&sp, g_sc);
    cudaGetSymbolAddress((void**)&phi, g_phi);
    cudaGetSymbolAddress((void**)&ahi, g_ahi);

    cudaFuncSetAttribute(gemm_mma<0,1>, cudaFuncAttributeMaxDynamicSharedMemorySize, SMEM_SZ);
    cudaFuncSetAttribute(gemm_mma<1,1>, cudaFuncAttributeMaxDynamicSharedMemorySize, SMEM_SZ);
    cudaFuncSetAttribute(gemm_mma<2,1>, cudaFuncAttributeMaxDynamicSharedMemorySize, SMEM_SZ);

    const float scale = 0.08838834764831845f;  // 1/sqrt(128)

    // 1) convert inputs to fp16 (hi only — all GEMMs are 1-pass now)
    split_k<0><<<16384, 256>>>((const float4*)x,  (__half2*)xhi,  nullptr, 4194304);
    split_k<0><<<16384, 256>>>((const float4*)wq, (__half2*)wqhi, nullptr, 4194304);
    split_k<0><<<4096,  256>>>((const float4*)wk, (__half2*)wkhi, nullptr, 1048576);
    split_k<0><<<4096,  256>>>((const float4*)wv, (__half2*)wvhi, nullptr, 1048576);
    split_k<0><<<16384, 256>>>((const float4*)wo, (__half2*)wohi, nullptr, 4194304);

    // 2) projections (1-pass fp16); Q and K fuse RoPE+hi in the epilogue
    gemm_mma<2,1><<<dim3(32, 32, 1), 256, SMEM_SZ>>>(          // q -> qhi (rope)
        xhi, nullptr, wqhi, nullptr, nullptr, qhi, nullptr, fc, fs,
        DIM_, DIM_, DIM_, DIM_, 1, 1, 0, 0, 0, 0, 0, 0, 1.0f, 0, 0);
    gemm_mma<2,1><<<dim3(8, 32, 1), 256, SMEM_SZ>>>(           // k -> khi (rope)
        xhi, nullptr, wkhi, nullptr, nullptr, khi, nullptr, fc, fs,
        DIM_, DIM_, DIM_, NKV_ * HD_, 1, 1, 0, 0, 0, 0, 0, 0, 1.0f, 0, 0);
    gemm_mma<0,1><<<dim3(8, 32, 1), 256, SMEM_SZ>>>(           // v -> vf (fp32)
        xhi, nullptr, wvhi, nullptr, vf, nullptr, nullptr, nullptr, nullptr,
        DIM_, DIM_, DIM_, NKV_ * HD_, 1, 1, 0, 0, 0, 0, 0, 0, 1.0f, 0, 0);

    // 3) V transpose (hi only)
    tsplit_v_k<<<dim3(S_ / 32, HD_ / 32, B_ * NKV_), 256>>>(vf, vthi);

    // 4) scores = scale * Q K^T  (causal tile skip, 1-pass)
    gemm_mma<0,1><<<dim3(16, 16, B_ * NH_), 256, SMEM_SZ>>>(
        qhi, nullptr, khi, nullptr, sp, nullptr, nullptr, nullptr, nullptr,
        HD_, NH_ * HD_, NKV_ * HD_, S_,
        NH_, 4,
        (long long)HD_, (long long)S_ * NH_ * HD_,
        (long long)HD_, (long long)S_ * NKV_ * HD_,
        (long long)S_ * S_, (long long)NH_ * S_ * S_,
        scale, 1, 0);

    // 5) softmax -> probs hi only (single-read, register-resident)
    softmax_k<<<B_ * NH_ * S_, 256>>>(sp, phi);

    // 6) attn = P V  (K capped causally; 1-pass; hi-only out)
    gemm_mma<1,1><<<dim3(1, 16, B_ * NH_), 256, SMEM_SZ>>>(
        phi, nullptr, vthi, nullptr, nullptr, ahi, nullptr, nullptr, nullptr,
        S_, S_, S_, NH_ * HD_,
        NH_, 4,
        (long long)S_ * S_, (long long)NH_ * S_ * S_,
        (long long)HD_ * S_, (long long)NKV_ * HD_ * S_,
        (long long)HD_, (long long)S_ * NH_ * HD_,
        1.0f, 0, 1);

    // 7) output projection (1-pass fp16, fp32 out)
    gemm_mma<0,1><<<dim3(32, 32, 1), 256, SMEM_SZ>>>(
        ahi, nullptr, wohi, nullptr, out, nullptr, nullptr, nullptr, nullptr,
        DIM_, DIM_, DIM_, DIM_, 1, 1, 0, 0, 0, 0, 0, 0, 1.0f, 0, 0);
}

// round 13
// speedup vs baseline: 3.6070x; 1.2297x over previous
#include <cuda_runtime.h>
#include <cuda_fp16.h>
#include <math.h>

// Problem constants
constexpr int B_   = 2;
constexpr int S_   = 2048;
constexpr int DIM_ = 4096;
constexpr int NH_  = 32;
constexpr int NKV_ = 8;
constexpr int HD_  = 128;

// ---------------------------------------------------------------------------
// Scratch (module-scope device arrays; allocation-free at launch time)
// scores / probs buffers are GONE: attention is fused (flash) now.
// ---------------------------------------------------------------------------
__device__ __half g_xhi[16777216];                       // x hi
__device__ __half g_wqhi[16777216];
__device__ __half g_wkhi[4194304];
__device__ __half g_wvhi[4194304];
__device__ __half g_wohi[16777216];
__device__ float  g_vf[4194304];                         // v fp32 (pre-transpose)
__device__ __half g_qhi[16777216];                       // q hi post-rope
__device__ __half g_khi[4194304];                        // k hi post-rope
__device__ __half g_vthi[4194304];                       // V transposed [b,kv,d,s]
__device__ __half g_ahi[16777216];                       // attn hi (out-proj 1-pass)

// ---------------------------------------------------------------------------
// PTX helpers — sm_80-era only (compute_103 virtual arch: NO tcgen05)
// ---------------------------------------------------------------------------
__device__ __forceinline__ unsigned smem_u32(const void* p) {
    return (unsigned)__cvta_generic_to_shared(p);
}
__device__ __forceinline__ void cpa16(unsigned dst, const void* src) {
    asm volatile("cp.async.cg.shared.global [%0], [%1], 16;" :: "r"(dst), "l"(src) : "memory");
}
__device__ __forceinline__ void cpa_commit() {
    asm volatile("cp.async.commit_group;" ::: "memory");
}
__device__ __forceinline__ void cpa_wait1() {
    asm volatile("cp.async.wait_group 1;" ::: "memory");
}
__device__ __forceinline__ void cpa_wait0() {
    asm volatile("cp.async.wait_group 0;" ::: "memory");
}
__device__ __forceinline__ void ldsm4(unsigned* r, unsigned a) {
    asm volatile("ldmatrix.sync.aligned.m8n8.x4.shared.b16 {%0,%1,%2,%3}, [%4];"
                 : "=r"(r[0]), "=r"(r[1]), "=r"(r[2]), "=r"(r[3]) : "r"(a));
}
__device__ __forceinline__ void mma16816(float* c, const unsigned* a, const unsigned* b) {
    asm volatile("mma.sync.aligned.m16n8k16.row.col.f32.f16.f16.f32 "
                 "{%0,%1,%2,%3}, {%4,%5,%6,%7}, {%8,%9}, {%0,%1,%2,%3};"
                 : "+f"(c[0]), "+f"(c[1]), "+f"(c[2]), "+f"(c[3])
                 : "r"(a[0]), "r"(a[1]), "r"(a[2]), "r"(a[3]), "r"(b[0]), "r"(b[1]));
}

// ===========================================================================
// GEMM machinery (projections only now)
// ===========================================================================
constexpr int PITCH   = 80;
constexpr int SUBT    = 128 * PITCH;
constexpr int STAGE   = 4 * SUBT;
constexpr int SMEM_SZ = 2 * STAGE;     // 81920 B

// EPI=0: fp32 C.  EPI=1: fp16 C.  EPI=2: RoPE -> fp16.
template <int EPI>
__global__ __launch_bounds__(256, 2)
void gemm_mma(const __half* __restrict__ Ahi, const __half* __restrict__ Bhi,
              float* __restrict__ Cf, __half* __restrict__ Chi,
              const float* __restrict__ cs, const float* __restrict__ sn,
              int K, int lda, int ldb, int ldc, float scale)
{
    const int bm0 = blockIdx.y * 128;
    const int bn0 = blockIdx.x * 128;

    extern __shared__ char smem[];
    const unsigned sb = smem_u32(smem);
    const int tid  = threadIdx.x;
    const int lane = tid & 31;
    const int wid  = tid >> 5;
    const int wm   = wid & 3;
    const int wn   = wid >> 2;

    const int nk = K >> 5;

    auto stage = [&](int si) {
        const unsigned base = sb + (si & 1) * STAGE;
        const int kc = si * 32;
        #pragma unroll
        for (int it = 0; it < 8; it++) {
            const int sub = it >> 1;
            if (sub == 1 || sub == 3) continue;      // hi-only operands
            const int w   = (tid + it * 256) & 511;
            const int row = w >> 2, seg = w & 3;
            const __half* src = (sub == 0)
                ? Ahi + (long long)(bm0 + row) * lda + kc + seg * 8
                : Bhi + (long long)(bn0 + row) * ldb + kc + seg * 8;
            cpa16(base + sub * SUBT + row * PITCH + seg * 16, src);
        }
    };

    float acc[2][8][4];
    #pragma unroll
    for (int i = 0; i < 2; i++)
        #pragma unroll
        for (int j = 0; j < 8; j++)
            #pragma unroll
            for (int e = 0; e < 4; e++) acc[i][j][e] = 0.0f;

    stage(0); cpa_commit();
    stage(1); cpa_commit();

    const int arow = wm * 32 + (lane & 15);
    const int asel = (lane >> 4);
    const int brow = wn * 64 + (lane & 7) + ((lane >> 4) << 3);
    const int bsel = (lane >> 3) & 1;

    for (int i = 0; i < nk; i++) {
        if (i + 1 < nk) cpa_wait1(); else cpa_wait0();
        __syncthreads();
        const unsigned base = sb + (i & 1) * STAGE;

        #pragma unroll
        for (int ks = 0; ks < 2; ks++) {
            unsigned ah[2][4];
            #pragma unroll
            for (int mt = 0; mt < 2; mt++)
                ldsm4(ah[mt], base + (arow + mt * 16) * PITCH + (ks * 2 + asel) * 16);
            #pragma unroll
            for (int pr = 0; pr < 4; pr++) {
                unsigned bh[4];
                ldsm4(bh, base + 2 * SUBT + (brow + pr * 16) * PITCH + (ks * 2 + bsel) * 16);
                #pragma unroll
                for (int mt = 0; mt < 2; mt++)
                    #pragma unroll
                    for (int hf = 0; hf < 2; hf++)
                        mma16816(acc[mt][pr * 2 + hf], ah[mt], &bh[hf * 2]);
            }
        }
        __syncthreads();
        if (i + 2 < nk) { stage(i + 2); cpa_commit(); }
    }

    const int er = bm0 + wm * 32 + (lane >> 2);
    const int ec = bn0 + wn * 64 + (lane & 3) * 2;
    #pragma unroll
    for (int mt = 0; mt < 2; mt++)
        #pragma unroll
        for (int nt = 0; nt < 8; nt++) {
            const float* c = acc[mt][nt];
            const int row = er + mt * 16;
            const int col = ec + nt * 8;
            const long long gi0 = (long long)row * ldc + col;
            const long long gi1 = (long long)(row + 8) * ldc + col;
            if (EPI == 0) {
                *(float2*)(Cf + gi0) = make_float2(c[0] * scale, c[1] * scale);
                *(float2*)(Cf + gi1) = make_float2(c[2] * scale, c[3] * scale);
            } else if (EPI == 1) {
                *(__half2*)(Chi + gi0) = __floats2half2_rn(c[0] * scale, c[1] * scale);
                *(__half2*)(Chi + gi1) = __floats2half2_rn(c[2] * scale, c[3] * scale);
            } else {
                const int ip  = (col & 127) >> 1;
                const int s0r = row & (S_ - 1);
                const int s1r = (row + 8) & (S_ - 1);
                const float c0 = cs[s0r * 64 + ip], sv0 = sn[s0r * 64 + ip];
                const float c1 = cs[s1r * 64 + ip], sv1 = sn[s1r * 64 + ip];
                *(__half2*)(Chi + gi0) = __floats2half2_rn(
                    c[0] * c0 - c[1] * sv0, c[0] * sv0 + c[1] * c0);
                *(__half2*)(Chi + gi1) = __floats2half2_rn(
                    c[2] * c1 - c[3] * sv1, c[2] * sv1 + c[3] * c1);
            }
        }
}

// ===========================================================================
// Fused flash attention: scores + causal online softmax + P*V in one kernel.
// Grid (16 q-blocks, B*NH). CTA 256 thr = 8 warps; warp owns 16 q-rows, full
// 128-col width (row stats reduce with 2 shfls). Q in regs; K/V tiles double-
// buffered in smem (272B pitch = conflict-free per ldsm 8-lane phase).
// S-accum fragments convert in-register to P fp16 A-fragments (C->A layout
// identity for m16n8 / m16n8k16).
// ===========================================================================
constexpr int FP    = 272;             // flash smem pitch (bytes per 128-half row)
constexpr int FTILE = 128 * FP;        // 34816 B per K or V tile
constexpr int FSMEM = 4 * FTILE;       // K0|V0|K1|V1 = 139264 B

__global__ __launch_bounds__(256, 1)
void flash_k(const __half* __restrict__ qhi, const __half* __restrict__ khi,
             const __half* __restrict__ vthi, __half* __restrict__ outp,
             float scale)
{
    const int bi = blockIdx.x;           // q block (rows bi*128..)
    const int bh = blockIdx.y;           // b*NH + h
    const int b  = bh >> 5, h = bh & 31;
    const int kv = h >> 2;               // GQA share
    const int bm0 = bi * 128;

    extern __shared__ char smem[];
    const unsigned sb = smem_u32(smem);
    const int tid = threadIdx.x, lane = tid & 31, w = tid >> 5;

    // ---- stage Q block into buffer 0, load fragments to registers
    #pragma unroll
    for (int it = 0; it < 8; it++) {
        const int idx = tid + it * 256;
        const int row = idx >> 4, seg = idx & 15;
        cpa16(sb + row * FP + seg * 16,
              qhi + ((size_t)((b * S_ + bm0 + row) * NH_ + h)) * HD_ + seg * 8);
    }
    cpa_commit(); cpa_wait0(); __syncthreads();

    unsigned qa[8][4];
    {
        const int ar = w * 16 + (lane & 15);
        const int as = lane >> 4;
        #pragma unroll
        for (int t = 0; t < 8; t++)
            ldsm4(qa[t], sb + ar * FP + (t * 2 + as) * 16);
    }
    __syncthreads();

    const int nk = bi + 1;
    auto stageKV = [&](int j) {
        const unsigned kb = sb + (j & 1) * (2 * FTILE);
        const unsigned vb = kb + FTILE;
        #pragma unroll
        for (int it = 0; it < 8; it++) {
            const int idx = tid + it * 256;
            const int row = idx >> 4, seg = idx & 15;
            cpa16(kb + row * FP + seg * 16,
                  khi + ((size_t)((b * S_ + j * 128 + row) * NKV_ + kv)) * HD_ + seg * 8);
            cpa16(vb + row * FP + seg * 16,
                  vthi + ((size_t)((b * NKV_ + kv) * HD_ + row)) * S_ + j * 128 + seg * 8);
        }
    };

    stageKV(0); cpa_commit();
    if (nk > 1) { stageKV(1); cpa_commit(); }

    float oacc[16][4];
    #pragma unroll
    for (int i = 0; i < 16; i++)
        #pragma unroll
        for (int e = 0; e < 4; e++) oacc[i][e] = 0.0f;
    float m0 = -1e30f, m1 = -1e30f, l0 = 0.0f, l1 = 0.0f;

    const int bro = (lane & 7) + ((lane >> 4) << 3);
    const int bsl = (lane >> 3) & 1;

    for (int j = 0; j < nk; j++) {
        if (j + 1 < nk) cpa_wait1(); else cpa_wait0();
        __syncthreads();
        const unsigned kb = sb + (j & 1) * (2 * FTILE);
        const unsigned vb = kb + FTILE;

        // ---- S = Q K^T  (raw, unscaled)
        float sacc[16][4];
        #pragma unroll
        for (int i = 0; i < 16; i++)
            #pragma unroll
            for (int e = 0; e < 4; e++) sacc[i][e] = 0.0f;
        #pragma unroll
        for (int t = 0; t < 8; t++)
            #pragma unroll
            for (int pn = 0; pn < 8; pn++) {
                unsigned bb[4];
                ldsm4(bb, kb + (pn * 16 + bro) * FP + (t * 2 + bsl) * 16);
                mma16816(sacc[2 * pn],     qa[t], bb);
                mma16816(sacc[2 * pn + 1], qa[t], bb + 2);
            }

        // ---- causal mask (diagonal tile only)
        if (j == bi) {
            const int r0 = w * 16 + (lane >> 2);
            const int cb = (lane & 3) * 2;
            #pragma unroll
            for (int nt = 0; nt < 16; nt++) {
                const int c0 = nt * 8 + cb;
                if (c0     > r0)     sacc[nt][0] = -1e30f;
                if (c0 + 1 > r0)     sacc[nt][1] = -1e30f;
                if (c0     > r0 + 8) sacc[nt][2] = -1e30f;
                if (c0 + 1 > r0 + 8) sacc[nt][3] = -1e30f;
            }
        }

        // ---- online softmax (rows r0 = lane>>2 and r0+8 within warp band)
        float mx0 = -1e30f, mx1 = -1e30f;
        #pragma unroll
        for (int nt = 0; nt < 16; nt++) {
            mx0 = fmaxf(mx0, fmaxf(sacc[nt][0], sacc[nt][1]));
            mx1 = fmaxf(mx1, fmaxf(sacc[nt][2], sacc[nt][3]));
        }
        mx0 = fmaxf(mx0, __shfl_xor_sync(0xffffffffu, mx0, 1));
        mx0 = fmaxf(mx0, __shfl_xor_sync(0xffffffffu, mx0, 2));
        mx1 = fmaxf(mx1, __shfl_xor_sync(0xffffffffu, mx1, 1));
        mx1 = fmaxf(mx1, __shfl_xor_sync(0xffffffffu, mx1, 2));
        const float mn0 = fmaxf(m0, mx0 * scale);
        const float mn1 = fmaxf(m1, mx1 * scale);
        const float a0 = expf(m0 - mn0);
        const float a1 = expf(m1 - mn1);
        m0 = mn0; m1 = mn1;
        #pragma unroll
        for (int nt = 0; nt < 16; nt++) {
            oacc[nt][0] *= a0; oacc[nt][1] *= a0;
            oacc[nt][2] *= a1; oacc[nt][3] *= a1;
        }

        float rs0 = 0.0f, rs1 = 0.0f;
        unsigned pa[8][4];
        #pragma unroll
        for (int t = 0; t < 8; t++) {
            const float e0 = expf(sacc[2 * t][0] * scale - mn0);
            const float e1 = expf(sacc[2 * t][1] * scale - mn0);
            const float e2 = expf(sacc[2 * t][2] * scale - mn1);
            const float e3 = expf(sacc[2 * t][3] * scale - mn1);
            const float f0 = expf(sacc[2 * t + 1][0] * scale - mn0);
            const float f1 = expf(sacc[2 * t + 1][1] * scale - mn0);
            const float f2 = expf(sacc[2 * t + 1][2] * scale - mn1);
            const float f3 = expf(sacc[2 * t + 1][3] * scale - mn1);
            rs0 += e0 + e1 + f0 + f1;
            rs1 += e2 + e3 + f2 + f3;
            __half2 p0 = __floats2half2_rn(e0, e1);
            __half2 p1 = __floats2half2_rn(e2, e3);
            __half2 p2 = __floats2half2_rn(f0, f1);
            __half2 p3 = __floats2half2_rn(f2, f3);
            pa[t][0] = *(unsigned*)&p0;   // a0: row r0,   k-lo
            pa[t][1] = *(unsigned*)&p1;   // a1: row r0+8, k-lo
            pa[t][2] = *(unsigned*)&p2;   // a2: row r0,   k-hi
            pa[t][3] = *(unsigned*)&p3;   // a3: row r0+8, k-hi
        }
        rs0 += __shfl_xor_sync(0xffffffffu, rs0, 1);
        rs0 += __shfl_xor_sync(0xffffffffu, rs0, 2);
        rs1 += __shfl_xor_sync(0xffffffffu, rs1, 1);
        rs1 += __shfl_xor_sync(0xffffffffu, rs1, 2);
        l0 = l0 * a0 + rs0;
        l1 = l1 * a1 + rs1;

        // ---- O += P V
        #pragma unroll
        for (int t = 0; t < 8; t++)
            #pragma unroll
            for (int pn = 0; pn < 8; pn++) {
                unsigned bb[4];
                ldsm4(bb, vb + (pn * 16 + bro) * FP + (t * 2 + bsl) * 16);
                mma16816(oacc[2 * pn],     pa[t], bb);
                mma16816(oacc[2 * pn + 1], pa[t], bb + 2);
            }

        __syncthreads();
        if (j + 2 < nk) { stageKV(j + 2); cpa_commit(); }
    }

    // ---- normalize + write O (fp16, [b,s,h,d])
    const float i0 = 1.0f / l0, i1 = 1.0f / l1;
    const int r0 = bm0 + w * 16 + (lane >> 2);
    const int cb = (lane & 3) * 2;
    #pragma unroll
    for (int nt = 0; nt < 16; nt++) {
        const int col = nt * 8 + cb;
        const size_t g0 = ((size_t)((b * S_ + r0) * NH_ + h)) * HD_ + col;
        const size_t g1 = ((size_t)((b * S_ + r0 + 8) * NH_ + h)) * HD_ + col;
        *(__half2*)(outp + g0) = __floats2half2_rn(oacc[nt][0] * i0, oacc[nt][1] * i0);
        *(__half2*)(outp + g1) = __floats2half2_rn(oacc[nt][2] * i1, oacc[nt][3] * i1);
    }
}

// ---------------------------------------------------------------------------
// Elementwise fp32 -> fp16
// ---------------------------------------------------------------------------
__global__ __launch_bounds__(256)
void split_k(const float4* __restrict__ s, __half2* __restrict__ h2, int n4)
{
    int i = blockIdx.x * 256 + threadIdx.x;
    if (i >= n4) return;
    float4 v = s[i];
    h2[2 * i]     = __floats2half2_rn(v.x, v.y);
    h2[2 * i + 1] = __floats2half2_rn(v.z, v.w);
}

// ---------------------------------------------------------------------------
// V transpose: vf32 [b,s,kv,d] -> vt fp16 [b,kv,d,s]
// ---------------------------------------------------------------------------
__global__ __launch_bounds__(256)
void tsplit_v_k(const float* __restrict__ v, __half* __restrict__ hi)
{
    __shared__ float tile[32][33];
    const int bz = blockIdx.z;
    const int b = bz >> 3, kv = bz & 7;
    const int s0 = blockIdx.x * 32, d0 = blockIdx.y * 32;
    const int tx = threadIdx.x & 31, ty = threadIdx.x >> 5;

    #pragma unroll
    for (int j = 0; j < 4; j++) {
        int s = s0 + ty + j * 8;
        tile[ty + j * 8][tx] = v[((size_t)(b * S_ + s) * NKV_ + kv) * HD_ + d0 + tx];
    }
    __syncthreads();
    #pragma unroll
    for (int j = 0; j < 4; j++) {
        int d = d0 + ty + j * 8;
        size_t o = ((size_t)(b * NKV_ + kv) * HD_ + d) * S_ + s0 + tx;
        hi[o] = __float2half(tile[tx][ty + j * 8]);
    }
}

// ---------------------------------------------------------------------------
// Inputs (metadata order): x, wq, wk, wv, wo, freqs_cos, freqs_sin
// ---------------------------------------------------------------------------
extern "C" void kernel_launch(void* const* d_in, const int* in_sizes, int n_in,
                              void* d_out, int out_size)
{
    const float* x  = (const float*)d_in[0];
    const float* wq = (const float*)d_in[1];
    const float* wk = (const float*)d_in[2];
    const float* wv = (const float*)d_in[3];
    const float* wo = (const float*)d_in[4];
    const float* fc = (const float*)d_in[5];
    const float* fs = (const float*)d_in[6];
    float* out = (float*)d_out;

    __half *xhi, *wqhi, *wkhi, *wvhi, *wohi;
    __half *qhi, *khi, *vthi, *ahi;
    float *vf;
    cudaGetSymbolAddress((void**)&xhi,  g_xhi);
    cudaGetSymbolAddress((void**)&wqhi, g_wqhi);
    cudaGetSymbolAddress((void**)&wkhi, g_wkhi);
    cudaGetSymbolAddress((void**)&wvhi, g_wvhi);
    cudaGetSymbolAddress((void**)&wohi, g_wohi);
    cudaGetSymbolAddress((void**)&vf, g_vf);
    cudaGetSymbolAddress((void**)&qhi, g_qhi);
    cudaGetSymbolAddress((void**)&khi, g_khi);
    cudaGetSymbolAddress((void**)&vthi, g_vthi);
    cudaGetSymbolAddress((void**)&ahi, g_ahi);

    cudaFuncSetAttribute(gemm_mma<0>, cudaFuncAttributeMaxDynamicSharedMemorySize, SMEM_SZ);
    cudaFuncSetAttribute(gemm_mma<1>, cudaFuncAttributeMaxDynamicSharedMemorySize, SMEM_SZ);
    cudaFuncSetAttribute(gemm_mma<2>, cudaFuncAttributeMaxDynamicSharedMemorySize, SMEM_SZ);
    cudaFuncSetAttribute(flash_k, cudaFuncAttributeMaxDynamicSharedMemorySize, FSMEM);

    const float scale = 0.08838834764831845f;  // 1/sqrt(128)

    // 1) convert inputs to fp16
    split_k<<<16384, 256>>>((const float4*)x,  (__half2*)xhi,  4194304);
    split_k<<<16384, 256>>>((const float4*)wq, (__half2*)wqhi, 4194304);
    split_k<<<4096,  256>>>((const float4*)wk, (__half2*)wkhi, 1048576);
    split_k<<<4096,  256>>>((const float4*)wv, (__half2*)wvhi, 1048576);
    split_k<<<16384, 256>>>((const float4*)wo, (__half2*)wohi, 4194304);

    // 2) projections; Q and K fuse RoPE in the epilogue
    gemm_mma<2><<<dim3(32, 32, 1), 256, SMEM_SZ>>>(
        xhi, wqhi, nullptr, qhi, fc, fs, DIM_, DIM_, DIM_, DIM_, 1.0f);
    gemm_mma<2><<<dim3(8, 32, 1), 256, SMEM_SZ>>>(
        xhi, wkhi, nullptr, khi, fc, fs, DIM_, DIM_, DIM_, NKV_ * HD_, 1.0f);
    gemm_mma<0><<<dim3(8, 32, 1), 256, SMEM_SZ>>>(
        xhi, wvhi, vf, nullptr, nullptr, nullptr, DIM_, DIM_, DIM_, NKV_ * HD_, 1.0f);

    // 3) V transpose
    tsplit_v_k<<<dim3(S_ / 32, HD_ / 32, B_ * NKV_), 256>>>(vf, vthi);

    // 4) fused flash attention (QK^T + causal online softmax + P V)
    flash_k<<<dim3(S_ / 128, B_ * NH_), 256, FSMEM>>>(qhi, khi, vthi, ahi, scale);

    // 5) output projection (fp32 out)
    gemm_mma<0><<<dim3(32, 32, 1), 256, SMEM_SZ>>>(
        ahi, wohi, out, nullptr, nullptr, nullptr, DIM_, DIM_, DIM_, DIM_, 1.0f);
}

// round 16
// speedup vs baseline: 3.8894x; 1.0783x over previous
#include <cuda_runtime.h>
#include <cuda_fp16.h>
#include <math.h>

// Problem constants
constexpr int B_   = 2;
constexpr int S_   = 2048;
constexpr int DIM_ = 4096;
constexpr int NH_  = 32;
constexpr int NKV_ = 8;
constexpr int HD_  = 128;
constexpr int KVW_ = NKV_ * HD_;       // 1024 (K/V projection width)
constexpr int NQKV = DIM_ + 2 * KVW_;  // 6144 fused projection width

// ---------------------------------------------------------------------------
// Scratch (module-scope device arrays; allocation-free at launch time)
// ---------------------------------------------------------------------------
__device__ __half g_xhi[16777216];                       // x fp16
__device__ __half g_wqkv[25165824];                      // [wq;wk;wv] rows, K-major (6144 x 4096)
__device__ __half g_wohi[16777216];
__device__ __half g_qhi[16777216];                       // q fp16 post-rope [b,s,h,d]
__device__ __half g_khi[4194304];                        // k fp16 post-rope [b,s,kv,d]
__device__ __half g_vthi[4194304];                       // V fp16 transposed [b,kv,d,s]
__device__ __half g_ahi[16777216];                       // attn fp16 [b,s,h,d]

// ---------------------------------------------------------------------------
// PTX helpers — sm_80-era only (compute_103 virtual arch: NO tcgen05)
// ---------------------------------------------------------------------------
__device__ __forceinline__ unsigned smem_u32(const void* p) {
    return (unsigned)__cvta_generic_to_shared(p);
}
__device__ __forceinline__ void cpa16(unsigned dst, const void* src) {
    asm volatile("cp.async.cg.shared.global [%0], [%1], 16;" :: "r"(dst), "l"(src) : "memory");
}
__device__ __forceinline__ void cpa_commit() {
    asm volatile("cp.async.commit_group;" ::: "memory");
}
__device__ __forceinline__ void cpa_wait1() {
    asm volatile("cp.async.wait_group 1;" ::: "memory");
}
__device__ __forceinline__ void cpa_wait0() {
    asm volatile("cp.async.wait_group 0;" ::: "memory");
}
__device__ __forceinline__ void ldsm4(unsigned* r, unsigned a) {
    asm volatile("ldmatrix.sync.aligned.m8n8.x4.shared.b16 {%0,%1,%2,%3}, [%4];"
                 : "=r"(r[0]), "=r"(r[1]), "=r"(r[2]), "=r"(r[3]) : "r"(a));
}
__device__ __forceinline__ void mma16816(float* c, const unsigned* a, const unsigned* b) {
    asm volatile("mma.sync.aligned.m16n8k16.row.col.f32.f16.f16.f32 "
                 "{%0,%1,%2,%3}, {%4,%5,%6,%7}, {%8,%9}, {%0,%1,%2,%3};"
                 : "+f"(c[0]), "+f"(c[1]), "+f"(c[2]), "+f"(c[3])
                 : "r"(a[0]), "r"(a[1]), "r"(a[2]), "r"(a[3]), "r"(b[0]), "r"(b[1]));
}

// ===========================================================================
// Projection GEMM, KC = 64 (halved iteration/barrier count vs KC=32).
// SMEM: rows of 64 halves (128B) padded to 144B pitch.
// EPI=0: fp32 C (out-proj).
// EPI=3: fused QKV epilogue: col<4096 RoPE->qhi; col<5120 RoPE->khi;
//        else V written fp16 DIRECTLY TRANSPOSED into vthi [b,kv,d,s].
// ===========================================================================
constexpr int GPITCH = 144;
constexpr int GSUBT  = 128 * GPITCH;   // 18432 B per operand
constexpr int GSTAGE = 2 * GSUBT;      // 36864 B
constexpr int GSMEM  = 2 * GSTAGE;     // 73728 B (2 CTAs/SM = 147456 <= 228K)

template <int EPI>
__global__ __launch_bounds__(256, 2)
void gemm64(const __half* __restrict__ A, const __half* __restrict__ Bm,
            float* __restrict__ Cf,
            __half* __restrict__ qp, __half* __restrict__ kp, __half* __restrict__ vp,
            const float* __restrict__ cs, const float* __restrict__ sn,
            int K, int lda, int ldb, int ldc)
{
    const int bm0 = blockIdx.y * 128;
    const int bn0 = blockIdx.x * 128;

    extern __shared__ char smem[];
    const unsigned sb = smem_u32(smem);
    const int tid  = threadIdx.x;
    const int lane = tid & 31;
    const int wid  = tid >> 5;
    const int wm   = wid & 3;
    const int wn   = wid >> 2;

    const int nk = K >> 6;

    auto stage = [&](int si) {
        const unsigned base = sb + (si & 1) * GSTAGE;
        const int kc = si * 64;
        #pragma unroll
        for (int it = 0; it < 8; it++) {
            const int w   = tid + (it & 3) * 256;   // 0..1023
            const int row = w >> 3, seg = w & 7;
            const __half* src = (it < 4)
                ? A  + (long long)(bm0 + row) * lda + kc + seg * 8
                : Bm + (long long)(bn0 + row) * ldb + kc + seg * 8;
            cpa16(base + (it < 4 ? 0u : (unsigned)GSUBT) + row * GPITCH + seg * 16, src);
        }
    };

    float acc[2][8][4];
    #pragma unroll
    for (int i = 0; i < 2; i++)
        #pragma unroll
        for (int j = 0; j < 8; j++)
            #pragma unroll
            for (int e = 0; e < 4; e++) acc[i][j][e] = 0.0f;

    stage(0); cpa_commit();
    stage(1); cpa_commit();

    const int arow = wm * 32 + (lane & 15);
    const int asel = (lane >> 4);
    const int brow = wn * 64 + (lane & 7) + ((lane >> 4) << 3);
    const int bsel = (lane >> 3) & 1;

    for (int i = 0; i < nk; i++) {
        if (i + 1 < nk) cpa_wait1(); else cpa_wait0();
        __syncthreads();
        const unsigned base = sb + (i & 1) * GSTAGE;

        #pragma unroll
        for (int ks = 0; ks < 4; ks++) {
            unsigned ah[2][4];
            #pragma unroll
            for (int mt = 0; mt < 2; mt++)
                ldsm4(ah[mt], base + (arow + mt * 16) * GPITCH + (ks * 2 + asel) * 16);
            #pragma unroll
            for (int pr = 0; pr < 4; pr++) {
                unsigned bh[4];
                ldsm4(bh, base + GSUBT + (brow + pr * 16) * GPITCH + (ks * 2 + bsel) * 16);
                #pragma unroll
                for (int mt = 0; mt < 2; mt++)
                    #pragma unroll
                    for (int hf = 0; hf < 2; hf++)
                        mma16816(acc[mt][pr * 2 + hf], ah[mt], &bh[hf * 2]);
            }
        }
        __syncthreads();
        if (i + 2 < nk) { stage(i + 2); cpa_commit(); }
    }

    // Epilogue
    const int er = bm0 + wm * 32 + (lane >> 2);
    const int ec = bn0 + wn * 64 + (lane & 3) * 2;
    #pragma unroll
    for (int mt = 0; mt < 2; mt++)
        #pragma unroll
        for (int nt = 0; nt < 8; nt++) {
            const float* c = acc[mt][nt];
            const int row = er + mt * 16;
            const int col = ec + nt * 8;
            if (EPI == 0) {
                const long long gi0 = (long long)row * ldc + col;
                const long long gi1 = (long long)(row + 8) * ldc + col;
                *(float2*)(Cf + gi0) = make_float2(c[0], c[1]);
                *(float2*)(Cf + gi1) = make_float2(c[2], c[3]);
            } else {
                const int s0r = row & (S_ - 1);
                const int s1r = (row + 8) & (S_ - 1);
                if (col < DIM_) {                      // ---- Q: RoPE -> qhi
                    const int ip = (col & 127) >> 1;
                    const float c0 = cs[s0r * 64 + ip], sv0 = sn[s0r * 64 + ip];
                    const float c1 = cs[s1r * 64 + ip], sv1 = sn[s1r * 64 + ip];
                    *(__half2*)(qp + (long long)row * DIM_ + col) =
                        __floats2half2_rn(c[0] * c0 - c[1] * sv0, c[0] * sv0 + c[1] * c0);
                    *(__half2*)(qp + (long long)(row + 8) * DIM_ + col) =
                        __floats2half2_rn(c[2] * c1 - c[3] * sv1, c[2] * sv1 + c[3] * c1);
                } else if (col < DIM_ + KVW_) {        // ---- K: RoPE -> khi
                    const int c2 = col - DIM_;         // 0..1023 = kv*128 + d
                    const int ip = (c2 & 127) >> 1;
                    const float c0 = cs[s0r * 64 + ip], sv0 = sn[s0r * 64 + ip];
                    const float c1 = cs[s1r * 64 + ip], sv1 = sn[s1r * 64 + ip];
                    *(__half2*)(kp + (long long)row * KVW_ + c2) =
                        __floats2half2_rn(c[0] * c0 - c[1] * sv0, c[0] * sv0 + c[1] * c0);
                    *(__half2*)(kp + (long long)(row + 8) * KVW_ + c2) =
                        __floats2half2_rn(c[2] * c1 - c[3] * sv1, c[2] * sv1 + c[3] * c1);
                } else {                               // ---- V: fp16 transposed -> vthi
                    const int c3 = col - (DIM_ + KVW_); // 0..1023
                    const int kv = c3 >> 7, d = c3 & 127;
                    const int b  = row >> 11;
                    const size_t base = ((size_t)(b * NKV_ + kv) * HD_ + d) * S_ + s0r;
                    vp[base]           = __float2half(c[0]);   // (d,   s)
                    vp[base + S_]      = __float2half(c[1]);   // (d+1, s)
                    vp[base + 8]       = __float2half(c[2]);   // (d,   s+8)
                    vp[base + S_ + 8]  = __float2half(c[3]);   // (d+1, s+8)
                }
            }
        }
}

// ===========================================================================
// Fused flash attention (unchanged from round 13 — validated).
// ===========================================================================
constexpr int FP    = 272;
constexpr int FTILE = 128 * FP;
constexpr int FSMEM = 4 * FTILE;       // 139264 B

__global__ __launch_bounds__(256, 1)
void flash_k(const __half* __restrict__ qhi, const __half* __restrict__ khi,
             const __half* __restrict__ vthi, __half* __restrict__ outp,
             float scale)
{
    const int bi = blockIdx.x;
    const int bh = blockIdx.y;
    const int b  = bh >> 5, h = bh & 31;
    const int kv = h >> 2;
    const int bm0 = bi * 128;

    extern __shared__ char smem[];
    const unsigned sb = smem_u32(smem);
    const int tid = threadIdx.x, lane = tid & 31, w = tid >> 5;

    #pragma unroll
    for (int it = 0; it < 8; it++) {
        const int idx = tid + it * 256;
        const int row = idx >> 4, seg = idx & 15;
        cpa16(sb + row * FP + seg * 16,
              qhi + ((size_t)((b * S_ + bm0 + row) * NH_ + h)) * HD_ + seg * 8);
    }
    cpa_commit(); cpa_wait0(); __syncthreads();

    unsigned qa[8][4];
    {
        const int ar = w * 16 + (lane & 15);
        const int as = lane >> 4;
        #pragma unroll
        for (int t = 0; t < 8; t++)
            ldsm4(qa[t], sb + ar * FP + (t * 2 + as) * 16);
    }
    __syncthreads();

    const int nk = bi + 1;
    auto stageKV = [&](int j) {
        const unsigned kb = sb + (j & 1) * (2 * FTILE);
        const unsigned vb = kb + FTILE;
        #pragma unroll
        for (int it = 0; it < 8; it++) {
            const int idx = tid + it * 256;
            const int row = idx >> 4, seg = idx & 15;
            cpa16(kb + row * FP + seg * 16,
                  khi + ((size_t)((b * S_ + j * 128 + row) * NKV_ + kv)) * HD_ + seg * 8);
            cpa16(vb + row * FP + seg * 16,
                  vthi + ((size_t)((b * NKV_ + kv) * HD_ + row)) * S_ + j * 128 + seg * 8);
        }
    };

    stageKV(0); cpa_commit();
    if (nk > 1) { stageKV(1); cpa_commit(); }

    float oacc[16][4];
    #pragma unroll
    for (int i = 0; i < 16; i++)
        #pragma unroll
        for (int e = 0; e < 4; e++) oacc[i][e] = 0.0f;
    float m0 = -1e30f, m1 = -1e30f, l0 = 0.0f, l1 = 0.0f;

    const int bro = (lane & 7) + ((lane >> 4) << 3);
    const int bsl = (lane >> 3) & 1;

    for (int j = 0; j < nk; j++) {
        if (j + 1 < nk) cpa_wait1(); else cpa_wait0();
        __syncthreads();
        const unsigned kb = sb + (j & 1) * (2 * FTILE);
        const unsigned vb = kb + FTILE;

        float sacc[16][4];
        #pragma unroll
        for (int i = 0; i < 16; i++)
            #pragma unroll
            for (int e = 0; e < 4; e++) sacc[i][e] = 0.0f;
        #pragma unroll
        for (int t = 0; t < 8; t++)
            #pragma unroll
            for (int pn = 0; pn < 8; pn++) {
                unsigned bb[4];
                ldsm4(bb, kb + (pn * 16 + bro) * FP + (t * 2 + bsl) * 16);
                mma16816(sacc[2 * pn],     qa[t], bb);
                mma16816(sacc[2 * pn + 1], qa[t], bb + 2);
            }

        if (j == bi) {
            const int r0 = w * 16 + (lane >> 2);
            const int cb = (lane & 3) * 2;
            #pragma unroll
            for (int nt = 0; nt < 16; nt++) {
                const int c0 = nt * 8 + cb;
                if (c0     > r0)     sacc[nt][0] = -1e30f;
                if (c0 + 1 > r0)     sacc[nt][1] = -1e30f;
                if (c0     > r0 + 8) sacc[nt][2] = -1e30f;
                if (c0 + 1 > r0 + 8) sacc[nt][3] = -1e30f;
            }
        }

        float mx0 = -1e30f, mx1 = -1e30f;
        #pragma unroll
        for (int nt = 0; nt < 16; nt++) {
            mx0 = fmaxf(mx0, fmaxf(sacc[nt][0], sacc[nt][1]));
            mx1 = fmaxf(mx1, fmaxf(sacc[nt][2], sacc[nt][3]));
        }
        mx0 = fmaxf(mx0, __shfl_xor_sync(0xffffffffu, mx0, 1));
        mx0 = fmaxf(mx0, __shfl_xor_sync(0xffffffffu, mx0, 2));
        mx1 = fmaxf(mx1, __shfl_xor_sync(0xffffffffu, mx1, 1));
        mx1 = fmaxf(mx1, __shfl_xor_sync(0xffffffffu, mx1, 2));
        const float mn0 = fmaxf(m0, mx0 * scale);
        const float mn1 = fmaxf(m1, mx1 * scale);
        const float a0 = expf(m0 - mn0);
        const float a1 = expf(m1 - mn1);
        m0 = mn0; m1 = mn1;
        #pragma unroll
        for (int nt = 0; nt < 16; nt++) {
            oacc[nt][0] *= a0; oacc[nt][1] *= a0;
            oacc[nt][2] *= a1; oacc[nt][3] *= a1;
        }

        float rs0 = 0.0f, rs1 = 0.0f;
        unsigned pa[8][4];
        #pragma unroll
        for (int t = 0; t < 8; t++) {
            const float e0 = expf(sacc[2 * t][0] * scale - mn0);
            const float e1 = expf(sacc[2 * t][1] * scale - mn0);
            const float e2 = expf(sacc[2 * t][2] * scale - mn1);
            const float e3 = expf(sacc[2 * t][3] * scale - mn1);
            const float f0 = expf(sacc[2 * t + 1][0] * scale - mn0);
            const float f1 = expf(sacc[2 * t + 1][1] * scale - mn0);
            const float f2 = expf(sacc[2 * t + 1][2] * scale - mn1);
            const float f3 = expf(sacc[2 * t + 1][3] * scale - mn1);
            rs0 += e0 + e1 + f0 + f1;
            rs1 += e2 + e3 + f2 + f3;
            __half2 p0 = __floats2half2_rn(e0, e1);
            __half2 p1 = __floats2half2_rn(e2, e3);
            __half2 p2 = __floats2half2_rn(f0, f1);
            __half2 p3 = __floats2half2_rn(f2, f3);
            pa[t][0] = *(unsigned*)&p0;
            pa[t][1] = *(unsigned*)&p1;
            pa[t][2] = *(unsigned*)&p2;
            pa[t][3] = *(unsigned*)&p3;
        }
        rs0 += __shfl_xor_sync(0xffffffffu, rs0, 1);
        rs0 += __shfl_xor_sync(0xffffffffu, rs0, 2);
        rs1 += __shfl_xor_sync(0xffffffffu, rs1, 1);
        rs1 += __shfl_xor_sync(0xffffffffu, rs1, 2);
        l0 = l0 * a0 + rs0;
        l1 = l1 * a1 + rs1;

        #pragma unroll
        for (int t = 0; t < 8; t++)
            #pragma unroll
            for (int pn = 0; pn < 8; pn++) {
                unsigned bb[4];
                ldsm4(bb, vb + (pn * 16 + bro) * FP + (t * 2 + bsl) * 16);
                mma16816(oacc[2 * pn],     pa[t], bb);
                mma16816(oacc[2 * pn + 1], pa[t], bb + 2);
            }

        __syncthreads();
        if (j + 2 < nk) { stageKV(j + 2); cpa_commit(); }
    }

    const float i0 = 1.0f / l0, i1 = 1.0f / l1;
    const int r0 = bm0 + w * 16 + (lane >> 2);
    const int cb = (lane & 3) * 2;
    #pragma unroll
    for (int nt = 0; nt < 16; nt++) {
        const int col = nt * 8 + cb;
        const size_t g0 = ((size_t)((b * S_ + r0) * NH_ + h)) * HD_ + col;
        const size_t g1 = ((size_t)((b * S_ + r0 + 8) * NH_ + h)) * HD_ + col;
        *(__half2*)(outp + g0) = __floats2half2_rn(oacc[nt][0] * i0, oacc[nt][1] * i0);
        *(__half2*)(outp + g1) = __floats2half2_rn(oacc[nt][2] * i1, oacc[nt][3] * i1);
    }
}

// ---------------------------------------------------------------------------
// Elementwise fp32 -> fp16
// ---------------------------------------------------------------------------
__global__ __launch_bounds__(256)
void split_k(const float4* __restrict__ s, __half2* __restrict__ h2, int n4)
{
    int i = blockIdx.x * 256 + threadIdx.x;
    if (i >= n4) return;
    float4 v = s[i];
    h2[2 * i]     = __floats2half2_rn(v.x, v.y);
    h2[2 * i + 1] = __floats2half2_rn(v.z, v.w);
}

// ---------------------------------------------------------------------------
// Inputs (metadata order): x, wq, wk, wv, wo, freqs_cos, freqs_sin
// ---------------------------------------------------------------------------
extern "C" void kernel_launch(void* const* d_in, const int* in_sizes, int n_in,
                              void* d_out, int out_size)
{
    const float* x  = (const float*)d_in[0];
    const float* wq = (const float*)d_in[1];
    const float* wk = (const float*)d_in[2];
    const float* wv = (const float*)d_in[3];
    const float* wo = (const float*)d_in[4];
    const float* fc = (const float*)d_in[5];
    const float* fs = (const float*)d_in[6];
    float* out = (float*)d_out;

    __half *xhi, *wqkv, *wohi, *qhi, *khi, *vthi, *ahi;
    cudaGetSymbolAddress((void**)&xhi,  g_xhi);
    cudaGetSymbolAddress((void**)&wqkv, g_wqkv);
    cudaGetSymbolAddress((void**)&wohi, g_wohi);
    cudaGetSymbolAddress((void**)&qhi,  g_qhi);
    cudaGetSymbolAddress((void**)&khi,  g_khi);
    cudaGetSymbolAddress((void**)&vthi, g_vthi);
    cudaGetSymbolAddress((void**)&ahi,  g_ahi);

    cudaFuncSetAttribute(gemm64<0>, cudaFuncAttributeMaxDynamicSharedMemorySize, GSMEM);
    cudaFuncSetAttribute(gemm64<3>, cudaFuncAttributeMaxDynamicSharedMemorySize, GSMEM);
    cudaFuncSetAttribute(flash_k, cudaFuncAttributeMaxDynamicSharedMemorySize, FSMEM);

    const float scale = 0.08838834764831845f;  // 1/sqrt(128)

    // 1) convert inputs to fp16 (wq|wk|wv concatenated: 4096 + 1024 + 1024 rows)
    split_k<<<16384, 256>>>((const float4*)x,  (__half2*)xhi,               4194304);
    split_k<<<16384, 256>>>((const float4*)wq, (__half2*)wqkv,              4194304);
    split_k<<<4096,  256>>>((const float4*)wk, (__half2*)(wqkv + 16777216), 1048576);
    split_k<<<4096,  256>>>((const float4*)wv, (__half2*)(wqkv + 20971520), 1048576);
    split_k<<<16384, 256>>>((const float4*)wo, (__half2*)wohi,              4194304);

    // 2) fused QKV projection (N=6144): Q->rope->qhi, K->rope->khi, V->vthi^T
    gemm64<3><<<dim3(NQKV / 128, 32), 256, GSMEM>>>(
        xhi, wqkv, nullptr, qhi, khi, vthi, fc, fs, DIM_, DIM_, DIM_, 0);

    // 3) fused flash attention (QK^T + causal online softmax + P V)
    flash_k<<<dim3(S_ / 128, B_ * NH_), 256, FSMEM>>>(qhi, khi, vthi, ahi, scale);

    // 4) output projection (fp32 out)
    gemm64<0><<<dim3(32, 32), 256, GSMEM>>>(
        ahi, wohi, out, nullptr, nullptr, nullptr, nullptr, nullptr,
        DIM_, DIM_, DIM_, DIM_);
}